// round 1
// baseline (speedup 1.0000x reference)
#include <cuda_runtime.h>
#include <math.h>

#define D     128
#define H     8
#define DKH   16
#define NMAX  50000
#define EMAX  800000

// ---------------- static device scratch (no allocations allowed) ----------------
__device__ float g_Q[NMAX * D];
__device__ float g_K[NMAX * D];
__device__ float g_V[NMAX * D];
__device__ float g_h[NMAX * D];        // h = x + res (attention output accumulates here)
__device__ float g_hn[NMAX * D];       // LayerNorm(h)
__device__ float g_act[NMAX * 2 * D];  // gelu(hn@W1+b1)
__device__ float g_ex[EMAX * H];       // exp(logit) per (edge, head)
__device__ float g_den[NMAX * H];      // softmax denominators per (dst, head)

// ---------------- init: h = x, den = 0 ----------------
__global__ void k_init(const float* __restrict__ x, int n) {
    int i = blockIdx.x * blockDim.x + threadIdx.x;
    if (i < n * D) g_h[i] = x[i];
    if (i < n * H) g_den[i] = 0.0f;
}

// ---------------- tiled SGEMM: C[nrows, ncols_tileN0..] = A[nrows,KA] @ B[KA,ncols] ----------------
// BM=BN=128, 256 threads, 8x8 per thread, K chunked by 32.
// EPI: 0 = +bias ; 1 = gelu(+bias) ; 2 = +bias + R[row,col] (residual)
template <int KA, int EPI>
__global__ __launch_bounds__(256)
void k_gemm(const float* __restrict__ A, const float* __restrict__ B,
            const float* __restrict__ bias, const float* __restrict__ R,
            float* __restrict__ C, int nrows, int ncols)
{
    __shared__ float As[32][132];   // [k][m] transposed, padded
    __shared__ float Bs[32][128];   // [k][n]

    const int tid = threadIdx.x;
    const int m0  = blockIdx.x * 128;
    const int n0  = blockIdx.y * 128;
    const int tm  = tid >> 4;      // 0..15
    const int tn  = tid & 15;      // 0..15

    float acc[8][8];
#pragma unroll
    for (int i = 0; i < 8; ++i)
#pragma unroll
        for (int j = 0; j < 8; ++j) acc[i][j] = 0.0f;

    const int ar = tid >> 3;            // base A row   (0..31)
    const int ac = (tid & 7) << 2;      // A k-offset   (0..28)
    const int br = tid >> 5;            // base B row   (0..7)
    const int bc = (tid & 31) << 2;     // B col offset (0..124)

    for (int kc = 0; kc < KA; kc += 32) {
        // load A tile (128 rows x 32 k), store transposed
#pragma unroll
        for (int p = 0; p < 4; ++p) {
            int m = ar + (p << 5);
            int grow = m0 + m;
            float4 av = make_float4(0.f, 0.f, 0.f, 0.f);
            if (grow < nrows)
                av = *(const float4*)(A + (size_t)grow * KA + kc + ac);
            As[ac + 0][m] = av.x;
            As[ac + 1][m] = av.y;
            As[ac + 2][m] = av.z;
            As[ac + 3][m] = av.w;
        }
        // load B tile (32 k x 128 n)
#pragma unroll
        for (int p = 0; p < 4; ++p) {
            int r = br + (p << 3);
            *(float4*)&Bs[r][bc] =
                *(const float4*)(B + (size_t)(kc + r) * ncols + n0 + bc);
        }
        __syncthreads();

#pragma unroll
        for (int kk = 0; kk < 32; ++kk) {
            float4 a0 = *(const float4*)&As[kk][tm * 8];
            float4 a1 = *(const float4*)&As[kk][tm * 8 + 4];
            float4 b0 = *(const float4*)&Bs[kk][tn * 8];
            float4 b1 = *(const float4*)&Bs[kk][tn * 8 + 4];
            float av[8] = {a0.x, a0.y, a0.z, a0.w, a1.x, a1.y, a1.z, a1.w};
            float bv[8] = {b0.x, b0.y, b0.z, b0.w, b1.x, b1.y, b1.z, b1.w};
#pragma unroll
            for (int i = 0; i < 8; ++i)
#pragma unroll
                for (int j = 0; j < 8; ++j)
                    acc[i][j] += av[i] * bv[j];
        }
        __syncthreads();
    }

    // epilogue
    const int cb = n0 + tn * 8;
    float4 bi0 = *(const float4*)(bias + cb);
    float4 bi1 = *(const float4*)(bias + cb + 4);
    float bb[8] = {bi0.x, bi0.y, bi0.z, bi0.w, bi1.x, bi1.y, bi1.z, bi1.w};

#pragma unroll
    for (int i = 0; i < 8; ++i) {
        int row = m0 + tm * 8 + i;
        if (row >= nrows) continue;
        float out[8];
#pragma unroll
        for (int j = 0; j < 8; ++j) {
            float v = acc[i][j] + bb[j];
            if (EPI == 1) {
                v = 0.5f * v * (1.0f + erff(v * 0.70710678118654752f));
            } else if (EPI == 2) {
                v += R[(size_t)row * ncols + cb + j];
            }
            out[j] = v;
        }
        *(float4*)(C + (size_t)row * ncols + cb)     = make_float4(out[0], out[1], out[2], out[3]);
        *(float4*)(C + (size_t)row * ncols + cb + 4) = make_float4(out[4], out[5], out[6], out[7]);
    }
}

// ---------------- edge logits: ex = exp(q[dst,h] . k[src,h] / 4); den[dst,h] += ex ----------------
__global__ void k_edge_logits(const int* __restrict__ ei, int E) {
    int t = blockIdx.x * blockDim.x + threadIdx.x;
    if (t >= E * H) return;
    int e = t >> 3;
    int h = t & 7;
    int src = __ldg(ei + e);
    int dst = __ldg(ei + E + e);
    const float4* q = (const float4*)(g_Q + (size_t)dst * D + h * DKH);
    const float4* k = (const float4*)(g_K + (size_t)src * D + h * DKH);
    float s = 0.0f;
#pragma unroll
    for (int i = 0; i < 4; ++i) {
        float4 qv = q[i], kv = k[i];
        s += qv.x * kv.x + qv.y * kv.y + qv.z * kv.z + qv.w * kv.w;
    }
    float ex = __expf(s * 0.25f);   // 1/sqrt(DK)=0.25 ; logits tiny -> max-shift unnecessary
    g_ex[t] = ex;
    atomicAdd(&g_den[dst * H + h], ex);
}

// ---------------- edge messages: h[dst,:] += v[src,:] * ex/(den+1e-16), warp per edge ----------------
__global__ void k_edge_msg(const int* __restrict__ ei, int E) {
    int gt = blockIdx.x * blockDim.x + threadIdx.x;
    int e = gt >> 5;
    if (e >= E) return;
    int lane = gt & 31;
    int src = __ldg(ei + e);
    int dst = __ldg(ei + E + e);
    int h = lane >> 2;   // 4 floats per lane, 16 per head
    float coeff = g_ex[e * H + h] / (g_den[dst * H + h] + 1e-16f);
    float4 v = *(const float4*)(g_V + (size_t)src * D + lane * 4);
    float* p = g_h + (size_t)dst * D + lane * 4;
    asm volatile("red.global.add.v4.f32 [%0], {%1, %2, %3, %4};" ::
                 "l"(p), "f"(v.x * coeff), "f"(v.y * coeff),
                 "f"(v.z * coeff), "f"(v.w * coeff)
                 : "memory");
}

// ---------------- LayerNorm: hn = (h-mu)*rsqrt(var+eps)*g + b, warp per row ----------------
__global__ void k_ln(const float* __restrict__ g, const float* __restrict__ b, int n) {
    int row = (blockIdx.x * blockDim.x + threadIdx.x) >> 5;
    int lane = threadIdx.x & 31;
    if (row >= n) return;
    float4 v = *(const float4*)(g_h + (size_t)row * D + lane * 4);
    float s = v.x + v.y + v.z + v.w;
#pragma unroll
    for (int o = 16; o > 0; o >>= 1) s += __shfl_xor_sync(0xffffffffu, s, o);
    float mu = s * (1.0f / 128.0f);
    float dx = v.x - mu, dy = v.y - mu, dz = v.z - mu, dw = v.w - mu;
    float vs = dx * dx + dy * dy + dz * dz + dw * dw;
#pragma unroll
    for (int o = 16; o > 0; o >>= 1) vs += __shfl_xor_sync(0xffffffffu, vs, o);
    float r = rsqrtf(vs * (1.0f / 128.0f) + 1e-5f);
    float4 gg = *(const float4*)(g + lane * 4);
    float4 bb = *(const float4*)(b + lane * 4);
    float4 o;
    o.x = dx * r * gg.x + bb.x;
    o.y = dy * r * gg.y + bb.y;
    o.z = dz * r * gg.z + bb.z;
    o.w = dw * r * gg.w + bb.w;
    *(float4*)(g_hn + (size_t)row * D + lane * 4) = o;
}

// ---------------- launch ----------------
extern "C" void kernel_launch(void* const* d_in, const int* in_sizes, int n_in,
                              void* d_out, int out_size) {
    const float* x    = (const float*)d_in[0];
    const int*   ei   = (const int*)  d_in[1];
    const float* Wq   = (const float*)d_in[2];
    const float* bq   = (const float*)d_in[3];
    const float* Wk   = (const float*)d_in[4];
    const float* bk   = (const float*)d_in[5];
    const float* Wv   = (const float*)d_in[6];
    const float* bv   = (const float*)d_in[7];
    const float* ln_g = (const float*)d_in[8];
    const float* ln_b = (const float*)d_in[9];
    const float* W1   = (const float*)d_in[10];
    const float* b1   = (const float*)d_in[11];
    const float* W2   = (const float*)d_in[12];
    const float* b2   = (const float*)d_in[13];
    float* out = (float*)d_out;

    const int n = in_sizes[0] / D;
    const int E = in_sizes[1] / 2;

    static float *pQ = nullptr, *pK, *pV, *ph, *phn, *pact;
    if (!pQ) {
        cudaGetSymbolAddress((void**)&pQ,   g_Q);
        cudaGetSymbolAddress((void**)&pK,   g_K);
        cudaGetSymbolAddress((void**)&pV,   g_V);
        cudaGetSymbolAddress((void**)&ph,   g_h);
        cudaGetSymbolAddress((void**)&phn,  g_hn);
        cudaGetSymbolAddress((void**)&pact, g_act);
    }

    // h = x ; den = 0
    k_init<<<(n * D + 255) / 256, 256>>>(x, n);

    // Q,K,V node projections
    dim3 gq((n + 127) / 128, 1);
    k_gemm<128, 0><<<gq, 256>>>(x, Wq, bq, nullptr, pQ, n, D);
    k_gemm<128, 0><<<gq, 256>>>(x, Wk, bk, nullptr, pK, n, D);
    k_gemm<128, 0><<<gq, 256>>>(x, Wv, bv, nullptr, pV, n, D);

    // attention logits + denominators
    k_edge_logits<<<(E * H + 255) / 256, 256>>>(ei, E);

    // scatter messages into h (h already holds x -> h = x + res)
    k_edge_msg<<<(E * 32 + 255) / 256, 256>>>(ei, E);

    // hn = LN(h)
    k_ln<<<(n * 32 + 255) / 256, 256>>>(ln_g, ln_b, n);

    // act = gelu(hn @ W1 + b1)     (ncols = 256 -> 2 column tiles)
    dim3 gf1((n + 127) / 128, 2);
    k_gemm<128, 1><<<gf1, 256>>>(phn, W1, b1, nullptr, pact, n, 2 * D);

    // out = h + act @ W2 + b2
    dim3 gf2((n + 127) / 128, 1);
    k_gemm<256, 2><<<gf2, 256>>>(pact, W2, b2, ph, out, n, D);
}

// round 2
// speedup vs baseline: 1.4663x; 1.4663x over previous
#include <cuda_runtime.h>
#include <math.h>

#define D     128
#define H     8
#define DKH   16
#define NMAX  50000
#define EMAX  800000

// ---------------- static device scratch ----------------
__device__ float g_Q[NMAX * D];
__device__ float g_K[NMAX * D];
__device__ float g_V[NMAX * D];
__device__ float g_h[NMAX * D];        // h = x + res
__device__ float g_hn[NMAX * D];       // LayerNorm(h)
__device__ float g_act[NMAX * 2 * D];  // gelu(hn@W1+b1)
__device__ float g_ex[EMAX * H];       // exp(logit) per (edge, head)
__device__ float g_den[NMAX * H];      // softmax denominators

// ---------------- init: h = x, den = 0 ----------------
__global__ void k_init(const float* __restrict__ x, int n) {
    int i = blockIdx.x * blockDim.x + threadIdx.x;
    if (i < n * D) g_h[i] = x[i];
    if (i < n * H) g_den[i] = 0.0f;
}

// ---------------- tf32 helpers ----------------
__device__ __forceinline__ unsigned f2tf32(float f) {
    unsigned u;
    asm("cvt.rna.tf32.f32 %0, %1;" : "=r"(u) : "f"(f));
    return u;
}

__device__ __forceinline__ void mma_tf32(float c[4],
    unsigned a0, unsigned a1, unsigned a2, unsigned a3,
    unsigned b0, unsigned b1)
{
    asm volatile(
        "mma.sync.aligned.m16n8k8.row.col.f32.tf32.tf32.f32 "
        "{%0,%1,%2,%3}, {%4,%5,%6,%7}, {%8,%9}, {%0,%1,%2,%3};"
        : "+f"(c[0]), "+f"(c[1]), "+f"(c[2]), "+f"(c[3])
        : "r"(a0), "r"(a1), "r"(a2), "r"(a3), "r"(b0), "r"(b1));
}

// ---------------- tensor-core GEMM body ----------------
// C[128 rows, 128 cols @ n0] = A[nrows,KA] @ B[KA,ncols], tf32 mma, fp32 accum.
// 256 threads = 8 warps (2x4), warp tile 64x32, BK=32.
// EPI: 0 = +bias ; 1 = gelu(+bias) ; 2 = +bias + R (residual)
template <int KA, int EPI>
__device__ __forceinline__ void gemm_body(
    const float* __restrict__ A, const float* __restrict__ B,
    const float* __restrict__ bias, const float* __restrict__ R,
    float* __restrict__ C, int nrows, int ncols, int n0)
{
    __shared__ unsigned As[128][36];   // [m][k] pad-36: banks (4g+tig) unique
    __shared__ unsigned Bs[32][132];   // [k][n] pad-132: banks (4tig+g) unique

    const int tid  = threadIdx.x;
    const int m0   = blockIdx.x * 128;
    const int w    = tid >> 5;
    const int lane = tid & 31;
    const int g    = lane >> 2;      // 0..7
    const int tig  = lane & 3;       // 0..3
    const int wm   = (w >> 2) * 64;  // 0 / 64
    const int wn   = (w & 3) * 32;   // 0 / 32 / 64 / 96

    float acc[4][4][4];
#pragma unroll
    for (int i = 0; i < 4; ++i)
#pragma unroll
        for (int j = 0; j < 4; ++j)
#pragma unroll
            for (int q = 0; q < 4; ++q) acc[i][j][q] = 0.0f;

    const int arow = tid >> 3;          // 0..31 (+32*p)
    const int acol = (tid & 7) << 2;    // 0..28
    const int brow = tid >> 5;          // 0..7  (+8*p)
    const int bcol = (tid & 31) << 2;   // 0..124

    for (int kc = 0; kc < KA; kc += 32) {
        // ---- load A tile 128x32 (tf32-rounded) ----
#pragma unroll
        for (int p = 0; p < 4; ++p) {
            int r = arow + (p << 5);
            float4 v = make_float4(0.f, 0.f, 0.f, 0.f);
            if (m0 + r < nrows)
                v = *(const float4*)(A + (size_t)(m0 + r) * KA + kc + acol);
            uint4 u = make_uint4(f2tf32(v.x), f2tf32(v.y), f2tf32(v.z), f2tf32(v.w));
            *(uint4*)&As[r][acol] = u;
        }
        // ---- load B tile 32x128 ----
#pragma unroll
        for (int p = 0; p < 4; ++p) {
            int r = brow + (p << 3);
            float4 v = *(const float4*)(B + (size_t)(kc + r) * ncols + n0 + bcol);
            uint4 u = make_uint4(f2tf32(v.x), f2tf32(v.y), f2tf32(v.z), f2tf32(v.w));
            *(uint4*)&Bs[r][bcol] = u;
        }
        __syncthreads();

#pragma unroll
        for (int ks = 0; ks < 4; ++ks) {
            const int kk = ks * 8;
            unsigned af[4][4];
#pragma unroll
            for (int ms = 0; ms < 4; ++ms) {
                int row = wm + ms * 16 + g;
                af[ms][0] = As[row][kk + tig];
                af[ms][1] = As[row + 8][kk + tig];
                af[ms][2] = As[row][kk + tig + 4];
                af[ms][3] = As[row + 8][kk + tig + 4];
            }
            unsigned bf[4][2];
#pragma unroll
            for (int ns = 0; ns < 4; ++ns) {
                int col = wn + ns * 8 + g;
                bf[ns][0] = Bs[kk + tig][col];
                bf[ns][1] = Bs[kk + tig + 4][col];
            }
#pragma unroll
            for (int ms = 0; ms < 4; ++ms)
#pragma unroll
                for (int ns = 0; ns < 4; ++ns)
                    mma_tf32(acc[ms][ns], af[ms][0], af[ms][1], af[ms][2], af[ms][3],
                             bf[ns][0], bf[ns][1]);
        }
        __syncthreads();
    }

    // ---- epilogue ----
#pragma unroll
    for (int ms = 0; ms < 4; ++ms) {
        int row0 = m0 + wm + ms * 16 + g;
#pragma unroll
        for (int half = 0; half < 2; ++half) {
            int row = row0 + half * 8;
            if (row >= nrows) continue;
#pragma unroll
            for (int ns = 0; ns < 4; ++ns) {
                int col = n0 + wn + ns * 8 + tig * 2;
                float v0 = acc[ms][ns][half * 2 + 0] + __ldg(bias + col);
                float v1 = acc[ms][ns][half * 2 + 1] + __ldg(bias + col + 1);
                if (EPI == 1) {
                    v0 = 0.5f * v0 * (1.0f + erff(v0 * 0.70710678118654752f));
                    v1 = 0.5f * v1 * (1.0f + erff(v1 * 0.70710678118654752f));
                } else if (EPI == 2) {
                    const float2 r2 = *(const float2*)(R + (size_t)row * ncols + col);
                    v0 += r2.x; v1 += r2.y;
                }
                *(float2*)(C + (size_t)row * ncols + col) = make_float2(v0, v1);
            }
        }
    }
}

template <int KA, int EPI>
__global__ __launch_bounds__(256, 2)
void k_gemm_tc(const float* __restrict__ A, const float* __restrict__ B,
               const float* __restrict__ bias, const float* __restrict__ R,
               float* __restrict__ C, int nrows, int ncols)
{
    gemm_body<KA, EPI>(A, B, bias, R, C, nrows, ncols, blockIdx.y * 128);
}

// fused QKV: blockIdx.z selects the weight/bias/output triple
__global__ __launch_bounds__(256, 2)
void k_gemm_qkv(const float* __restrict__ A,
                const float* __restrict__ B0, const float* __restrict__ B1,
                const float* __restrict__ B2,
                const float* __restrict__ b0, const float* __restrict__ b1,
                const float* __restrict__ b2,
                float* __restrict__ C0, float* __restrict__ C1,
                float* __restrict__ C2, int nrows)
{
    const float* B  = (blockIdx.z == 0) ? B0 : (blockIdx.z == 1) ? B1 : B2;
    const float* bi = (blockIdx.z == 0) ? b0 : (blockIdx.z == 1) ? b1 : b2;
    float*       C  = (blockIdx.z == 0) ? C0 : (blockIdx.z == 1) ? C1 : C2;
    gemm_body<128, 0>(A, B, bi, nullptr, C, nrows, 128, 0);
}

// ---------------- edge logits: ex = exp(q.k/4); den[dst,h] += ex ----------------
__global__ void k_edge_logits(const int* __restrict__ ei, int E) {
    int t = blockIdx.x * blockDim.x + threadIdx.x;
    if (t >= E * H) return;
    int e = t >> 3;
    int h = t & 7;
    int src = __ldg(ei + e);
    int dst = __ldg(ei + E + e);
    const float4* q = (const float4*)(g_Q + (size_t)dst * D + h * DKH);
    const float4* k = (const float4*)(g_K + (size_t)src * D + h * DKH);
    float s = 0.0f;
#pragma unroll
    for (int i = 0; i < 4; ++i) {
        float4 qv = q[i], kv = k[i];
        s += qv.x * kv.x + qv.y * kv.y + qv.z * kv.z + qv.w * kv.w;
    }
    float ex = __expf(s * 0.25f);
    g_ex[t] = ex;
    atomicAdd(&g_den[dst * H + h], ex);
}

// ---------------- edge messages: h[dst,:] += v[src,:] * ex/den, warp/edge ----------------
__global__ void k_edge_msg(const int* __restrict__ ei, int E) {
    int gt = blockIdx.x * blockDim.x + threadIdx.x;
    int e = gt >> 5;
    if (e >= E) return;
    int lane = gt & 31;
    int src = __ldg(ei + e);
    int dst = __ldg(ei + E + e);
    int h = lane >> 2;
    float coeff = g_ex[e * H + h] / (g_den[dst * H + h] + 1e-16f);
    float4 v = *(const float4*)(g_V + (size_t)src * D + lane * 4);
    float* p = g_h + (size_t)dst * D + lane * 4;
    asm volatile("red.global.add.v4.f32 [%0], {%1, %2, %3, %4};" ::
                 "l"(p), "f"(v.x * coeff), "f"(v.y * coeff),
                 "f"(v.z * coeff), "f"(v.w * coeff)
                 : "memory");
}

// ---------------- LayerNorm ----------------
__global__ void k_ln(const float* __restrict__ g, const float* __restrict__ b, int n) {
    int row = (blockIdx.x * blockDim.x + threadIdx.x) >> 5;
    int lane = threadIdx.x & 31;
    if (row >= n) return;
    float4 v = *(const float4*)(g_h + (size_t)row * D + lane * 4);
    float s = v.x + v.y + v.z + v.w;
#pragma unroll
    for (int o = 16; o > 0; o >>= 1) s += __shfl_xor_sync(0xffffffffu, s, o);
    float mu = s * (1.0f / 128.0f);
    float dx = v.x - mu, dy = v.y - mu, dz = v.z - mu, dw = v.w - mu;
    float vs = dx * dx + dy * dy + dz * dz + dw * dw;
#pragma unroll
    for (int o = 16; o > 0; o >>= 1) vs += __shfl_xor_sync(0xffffffffu, vs, o);
    float r = rsqrtf(vs * (1.0f / 128.0f) + 1e-5f);
    float4 gg = *(const float4*)(g + lane * 4);
    float4 bb = *(const float4*)(b + lane * 4);
    float4 o;
    o.x = dx * r * gg.x + bb.x;
    o.y = dy * r * gg.y + bb.y;
    o.z = dz * r * gg.z + bb.z;
    o.w = dw * r * gg.w + bb.w;
    *(float4*)(g_hn + (size_t)row * D + lane * 4) = o;
}

// ---------------- launch ----------------
extern "C" void kernel_launch(void* const* d_in, const int* in_sizes, int n_in,
                              void* d_out, int out_size) {
    const float* x    = (const float*)d_in[0];
    const int*   ei   = (const int*)  d_in[1];
    const float* Wq   = (const float*)d_in[2];
    const float* bq   = (const float*)d_in[3];
    const float* Wk   = (const float*)d_in[4];
    const float* bk   = (const float*)d_in[5];
    const float* Wv   = (const float*)d_in[6];
    const float* bv   = (const float*)d_in[7];
    const float* ln_g = (const float*)d_in[8];
    const float* ln_b = (const float*)d_in[9];
    const float* W1   = (const float*)d_in[10];
    const float* b1   = (const float*)d_in[11];
    const float* W2   = (const float*)d_in[12];
    const float* b2   = (const float*)d_in[13];
    float* out = (float*)d_out;

    const int n = in_sizes[0] / D;
    const int E = in_sizes[1] / 2;

    static float *pQ = nullptr, *pK, *pV, *ph, *phn, *pact;
    if (!pQ) {
        cudaGetSymbolAddress((void**)&pQ,   g_Q);
        cudaGetSymbolAddress((void**)&pK,   g_K);
        cudaGetSymbolAddress((void**)&pV,   g_V);
        cudaGetSymbolAddress((void**)&ph,   g_h);
        cudaGetSymbolAddress((void**)&phn,  g_hn);
        cudaGetSymbolAddress((void**)&pact, g_act);
    }

    // h = x ; den = 0
    k_init<<<(n * D + 255) / 256, 256>>>(x, n);

    // fused Q,K,V projections (tf32 tensor cores)
    dim3 gq((n + 127) / 128, 1, 3);
    k_gemm_qkv<<<gq, 256>>>(x, Wq, Wk, Wv, bq, bk, bv, pQ, pK, pV, n);

    // attention logits + denominators
    k_edge_logits<<<(E * H + 255) / 256, 256>>>(ei, E);

    // scatter messages into h (h holds x -> h = x + res)
    k_edge_msg<<<(E * 32 + 255) / 256, 256>>>(ei, E);

    // hn = LN(h)
    k_ln<<<(n * 32 + 255) / 256, 256>>>(ln_g, ln_b, n);

    // act = gelu(hn @ W1 + b1)
    dim3 gf1((n + 127) / 128, 2);
    k_gemm_tc<128, 1><<<gf1, 256>>>(phn, W1, b1, nullptr, pact, n, 2 * D);

    // out = h + act @ W2 + b2
    dim3 gf2((n + 127) / 128, 1);
    k_gemm_tc<256, 2><<<gf2, 256>>>(pact, W2, b2, ph, out, n, D);
}

// round 3
// speedup vs baseline: 2.0581x; 1.4037x over previous
#include <cuda_runtime.h>
#include <math.h>

#define D     128
#define H     8
#define NMAX  50000
#define EMAX  800000

// ---------------- static device scratch ----------------
__device__ float g_Q[NMAX * D];
__device__ float g_K[NMAX * D];
__device__ float g_V[NMAX * D];
__device__ float g_h[NMAX * D];        // h = x + attn residual
__device__ float g_hn[NMAX * D];       // LayerNorm(h)
__device__ float g_act[NMAX * 2 * D];  // gelu(hn@W1+b1)
__device__ int   g_cnt[NMAX];          // per-dst degree
__device__ int   g_off[NMAX + 1];      // exclusive prefix (segment starts)
__device__ int   g_cur[NMAX];          // scatter cursors
__device__ int   g_srt[EMAX];          // src ids sorted by dst

// ---------------- sort phase ----------------
__global__ void k_zero(int n) {
    int i = blockIdx.x * blockDim.x + threadIdx.x;
    if (i < n) g_cnt[i] = 0;
}

__global__ void k_hist(const int* __restrict__ ei, int E) {
    int e = blockIdx.x * blockDim.x + threadIdx.x;
    if (e < E) atomicAdd(&g_cnt[__ldg(ei + E + e)], 1);
}

// single-block scan over n counters -> g_off (exclusive) and g_cur (copy)
__global__ __launch_bounds__(1024)
void k_scan(int n) {
    __shared__ int warp_sums[32];
    __shared__ int s_carry;
    const int tid = threadIdx.x, lane = tid & 31, w = tid >> 5;
    if (tid == 0) s_carry = 0;
    __syncthreads();
    for (int base = 0; base < n; base += 1024) {
        int i = base + tid;
        int v = (i < n) ? g_cnt[i] : 0;
        int x = v;
#pragma unroll
        for (int o = 1; o < 32; o <<= 1) {
            int y = __shfl_up_sync(~0u, x, o);
            if (lane >= o) x += y;
        }
        if (lane == 31) warp_sums[w] = x;
        __syncthreads();
        if (w == 0) {
            int s = warp_sums[lane];
#pragma unroll
            for (int o = 1; o < 32; o <<= 1) {
                int y = __shfl_up_sync(~0u, s, o);
                if (lane >= o) s += y;
            }
            warp_sums[lane] = s;
        }
        __syncthreads();
        int incl = x + (w > 0 ? warp_sums[w - 1] : 0) + s_carry;
        int excl = incl - v;
        if (i < n) { g_off[i] = excl; g_cur[i] = excl; }
        __syncthreads();
        if (tid == 1023) s_carry = incl;
        __syncthreads();
    }
    if (tid == 0) g_off[n] = s_carry;
}

__global__ void k_scatter(const int* __restrict__ ei, int E) {
    int e = blockIdx.x * blockDim.x + threadIdx.x;
    if (e >= E) return;
    int src = __ldg(ei + e);
    int dst = __ldg(ei + E + e);
    int pos = atomicAdd(&g_cur[dst], 1);
    g_srt[pos] = src;
}

// ---------------- tf32 helpers ----------------
__device__ __forceinline__ unsigned f2tf32(float f) {
    unsigned u;
    asm("cvt.rna.tf32.f32 %0, %1;" : "=r"(u) : "f"(f));
    return u;
}

__device__ __forceinline__ void mma_tf32(float c[4],
    unsigned a0, unsigned a1, unsigned a2, unsigned a3,
    unsigned b0, unsigned b1)
{
    asm volatile(
        "mma.sync.aligned.m16n8k8.row.col.f32.tf32.tf32.f32 "
        "{%0,%1,%2,%3}, {%4,%5,%6,%7}, {%8,%9}, {%0,%1,%2,%3};"
        : "+f"(c[0]), "+f"(c[1]), "+f"(c[2]), "+f"(c[3])
        : "r"(a0), "r"(a1), "r"(a2), "r"(a3), "r"(b0), "r"(b1));
}

// ---------------- tensor-core GEMM body (unchanged from R2) ----------------
template <int KA, int EPI>
__device__ __forceinline__ void gemm_body(
    const float* __restrict__ A, const float* __restrict__ B,
    const float* __restrict__ bias, const float* __restrict__ R,
    float* __restrict__ C, int nrows, int ncols, int n0)
{
    __shared__ unsigned As[128][36];
    __shared__ unsigned Bs[32][132];

    const int tid  = threadIdx.x;
    const int m0   = blockIdx.x * 128;
    const int w    = tid >> 5;
    const int lane = tid & 31;
    const int g    = lane >> 2;
    const int tig  = lane & 3;
    const int wm   = (w >> 2) * 64;
    const int wn   = (w & 3) * 32;

    float acc[4][4][4];
#pragma unroll
    for (int i = 0; i < 4; ++i)
#pragma unroll
        for (int j = 0; j < 4; ++j)
#pragma unroll
            for (int q = 0; q < 4; ++q) acc[i][j][q] = 0.0f;

    const int arow = tid >> 3;
    const int acol = (tid & 7) << 2;
    const int brow = tid >> 5;
    const int bcol = (tid & 31) << 2;

    for (int kc = 0; kc < KA; kc += 32) {
#pragma unroll
        for (int p = 0; p < 4; ++p) {
            int r = arow + (p << 5);
            float4 v = make_float4(0.f, 0.f, 0.f, 0.f);
            if (m0 + r < nrows)
                v = *(const float4*)(A + (size_t)(m0 + r) * KA + kc + acol);
            uint4 u = make_uint4(f2tf32(v.x), f2tf32(v.y), f2tf32(v.z), f2tf32(v.w));
            *(uint4*)&As[r][acol] = u;
        }
#pragma unroll
        for (int p = 0; p < 4; ++p) {
            int r = brow + (p << 3);
            float4 v = *(const float4*)(B + (size_t)(kc + r) * ncols + n0 + bcol);
            uint4 u = make_uint4(f2tf32(v.x), f2tf32(v.y), f2tf32(v.z), f2tf32(v.w));
            *(uint4*)&Bs[r][bcol] = u;
        }
        __syncthreads();

#pragma unroll
        for (int ks = 0; ks < 4; ++ks) {
            const int kk = ks * 8;
            unsigned af[4][4];
#pragma unroll
            for (int ms = 0; ms < 4; ++ms) {
                int row = wm + ms * 16 + g;
                af[ms][0] = As[row][kk + tig];
                af[ms][1] = As[row + 8][kk + tig];
                af[ms][2] = As[row][kk + tig + 4];
                af[ms][3] = As[row + 8][kk + tig + 4];
            }
            unsigned bf[4][2];
#pragma unroll
            for (int ns = 0; ns < 4; ++ns) {
                int col = wn + ns * 8 + g;
                bf[ns][0] = Bs[kk + tig][col];
                bf[ns][1] = Bs[kk + tig + 4][col];
            }
#pragma unroll
            for (int ms = 0; ms < 4; ++ms)
#pragma unroll
                for (int ns = 0; ns < 4; ++ns)
                    mma_tf32(acc[ms][ns], af[ms][0], af[ms][1], af[ms][2], af[ms][3],
                             bf[ns][0], bf[ns][1]);
        }
        __syncthreads();
    }

#pragma unroll
    for (int ms = 0; ms < 4; ++ms) {
        int row0 = m0 + wm + ms * 16 + g;
#pragma unroll
        for (int half = 0; half < 2; ++half) {
            int row = row0 + half * 8;
            if (row >= nrows) continue;
#pragma unroll
            for (int ns = 0; ns < 4; ++ns) {
                int col = n0 + wn + ns * 8 + tig * 2;
                float v0 = acc[ms][ns][half * 2 + 0] + __ldg(bias + col);
                float v1 = acc[ms][ns][half * 2 + 1] + __ldg(bias + col + 1);
                if (EPI == 1) {
                    v0 = 0.5f * v0 * (1.0f + erff(v0 * 0.70710678118654752f));
                    v1 = 0.5f * v1 * (1.0f + erff(v1 * 0.70710678118654752f));
                } else if (EPI == 2) {
                    const float2 r2 = *(const float2*)(R + (size_t)row * ncols + col);
                    v0 += r2.x; v1 += r2.y;
                }
                *(float2*)(C + (size_t)row * ncols + col) = make_float2(v0, v1);
            }
        }
    }
}

template <int KA, int EPI>
__global__ __launch_bounds__(256, 2)
void k_gemm_tc(const float* __restrict__ A, const float* __restrict__ B,
               const float* __restrict__ bias, const float* __restrict__ R,
               float* __restrict__ C, int nrows, int ncols)
{
    gemm_body<KA, EPI>(A, B, bias, R, C, nrows, ncols, blockIdx.y * 128);
}

__global__ __launch_bounds__(256, 2)
void k_gemm_qkv(const float* __restrict__ A,
                const float* __restrict__ B0, const float* __restrict__ B1,
                const float* __restrict__ B2,
                const float* __restrict__ b0, const float* __restrict__ b1,
                const float* __restrict__ b2,
                float* __restrict__ C0, float* __restrict__ C1,
                float* __restrict__ C2, int nrows)
{
    const float* B  = (blockIdx.z == 0) ? B0 : (blockIdx.z == 1) ? B1 : B2;
    const float* bi = (blockIdx.z == 0) ? b0 : (blockIdx.z == 1) ? b1 : b2;
    float*       C  = (blockIdx.z == 0) ? C0 : (blockIdx.z == 1) ? C1 : C2;
    gemm_body<128, 0>(A, B, bi, nullptr, C, nrows, 128, 0);
}

// ---------------- fused attention + residual + LayerNorm, warp per dst node ----------------
// msg = (sum_e ex_e * V[src_e]) / (sum_e ex_e);  h = x + msg;  hn = LN(h)*g+b
__global__ __launch_bounds__(256)
void k_attn(const float* __restrict__ x,
            const float* __restrict__ lng, const float* __restrict__ lnb, int n)
{
    int row = (blockIdx.x * blockDim.x + threadIdx.x) >> 5;
    if (row >= n) return;
    const int lane = threadIdx.x & 31;

    // per-lane 4 dims; quad (lanes 4h..4h+3) = head h
    float4 q = *(const float4*)(g_Q + (size_t)row * D + lane * 4);
    float4 acc = make_float4(0.f, 0.f, 0.f, 0.f);
    float den = 0.0f;

    int beg = g_off[row], end = g_off[row + 1];
    for (int j = beg; j < end; ++j) {
        int src = g_srt[j];                     // warp-broadcast load
        const float4 k4 = *(const float4*)(g_K + (size_t)src * D + lane * 4);
        float s = q.x * k4.x + q.y * k4.y + q.z * k4.z + q.w * k4.w;
        s += __shfl_xor_sync(~0u, s, 1);
        s += __shfl_xor_sync(~0u, s, 2);        // head dot product in all 4 quad lanes
        float ex = __expf(s * 0.25f);           // 1/sqrt(16)
        den += ex;
        const float4 v4 = *(const float4*)(g_V + (size_t)src * D + lane * 4);
        acc.x += ex * v4.x; acc.y += ex * v4.y;
        acc.z += ex * v4.z; acc.w += ex * v4.w;
    }

    float inv = 1.0f / (den + 1e-16f);
    float4 xr = *(const float4*)(x + (size_t)row * D + lane * 4);
    float4 hv;
    hv.x = xr.x + acc.x * inv;
    hv.y = xr.y + acc.y * inv;
    hv.z = xr.z + acc.z * inv;
    hv.w = xr.w + acc.w * inv;
    *(float4*)(g_h + (size_t)row * D + lane * 4) = hv;

    // fused LayerNorm across the warp (row fully in registers)
    float s = hv.x + hv.y + hv.z + hv.w;
#pragma unroll
    for (int o = 16; o > 0; o >>= 1) s += __shfl_xor_sync(~0u, s, o);
    float mu = s * (1.0f / 128.0f);
    float dx = hv.x - mu, dy = hv.y - mu, dz = hv.z - mu, dw = hv.w - mu;
    float vs = dx * dx + dy * dy + dz * dz + dw * dw;
#pragma unroll
    for (int o = 16; o > 0; o >>= 1) vs += __shfl_xor_sync(~0u, vs, o);
    float r = rsqrtf(vs * (1.0f / 128.0f) + 1e-5f);
    float4 gg = *(const float4*)(lng + lane * 4);
    float4 bb = *(const float4*)(lnb + lane * 4);
    float4 o;
    o.x = dx * r * gg.x + bb.x;
    o.y = dy * r * gg.y + bb.y;
    o.z = dz * r * gg.z + bb.z;
    o.w = dw * r * gg.w + bb.w;
    *(float4*)(g_hn + (size_t)row * D + lane * 4) = o;
}

// ---------------- launch ----------------
extern "C" void kernel_launch(void* const* d_in, const int* in_sizes, int n_in,
                              void* d_out, int out_size) {
    const float* x    = (const float*)d_in[0];
    const int*   ei   = (const int*)  d_in[1];
    const float* Wq   = (const float*)d_in[2];
    const float* bq   = (const float*)d_in[3];
    const float* Wk   = (const float*)d_in[4];
    const float* bk   = (const float*)d_in[5];
    const float* Wv   = (const float*)d_in[6];
    const float* bv   = (const float*)d_in[7];
    const float* ln_g = (const float*)d_in[8];
    const float* ln_b = (const float*)d_in[9];
    const float* W1   = (const float*)d_in[10];
    const float* b1   = (const float*)d_in[11];
    const float* W2   = (const float*)d_in[12];
    const float* b2   = (const float*)d_in[13];
    float* out = (float*)d_out;

    const int n = in_sizes[0] / D;
    const int E = in_sizes[1] / 2;

    static float *pQ = nullptr, *pK, *pV, *ph, *phn, *pact;
    if (!pQ) {
        cudaGetSymbolAddress((void**)&pQ,   g_Q);
        cudaGetSymbolAddress((void**)&pK,   g_K);
        cudaGetSymbolAddress((void**)&pV,   g_V);
        cudaGetSymbolAddress((void**)&ph,   g_h);
        cudaGetSymbolAddress((void**)&phn,  g_hn);
        cudaGetSymbolAddress((void**)&pact, g_act);
    }

    // --- counting sort of edges by dst ---
    k_zero<<<(n + 255) / 256, 256>>>(n);
    k_hist<<<(E + 255) / 256, 256>>>(ei, E);
    k_scan<<<1, 1024>>>(n);
    k_scatter<<<(E + 255) / 256, 256>>>(ei, E);

    // --- fused Q,K,V projections (tf32 tensor cores) ---
    dim3 gq((n + 127) / 128, 1, 3);
    k_gemm_qkv<<<gq, 256>>>(x, Wq, Wk, Wv, bq, bk, bv, pQ, pK, pV, n);

    // --- fused attention + residual + LayerNorm ---
    k_attn<<<(n * 32 + 255) / 256, 256>>>(x, ln_g, ln_b, n);

    // --- FFN ---
    dim3 gf1((n + 127) / 128, 2);
    k_gemm_tc<128, 1><<<gf1, 256>>>(phn, W1, b1, nullptr, pact, n, 2 * D);

    dim3 gf2((n + 127) / 128, 1);
    k_gemm_tc<256, 2><<<gf2, 256>>>(pact, W2, b2, ph, out, n, D);
}

// round 4
// speedup vs baseline: 2.9441x; 1.4304x over previous
#include <cuda_runtime.h>
#include <cuda_bf16.h>
#include <math.h>

#define D     128
#define H     8
#define NMAX  50000
#define EMAX  800000

// ---------------- static device scratch ----------------
__device__ float g_Q[NMAX * D];
__device__ __nv_bfloat16 g_Kh[NMAX * D];
__device__ __nv_bfloat16 g_Vh[NMAX * D];
__device__ float g_h[NMAX * D];        // h = x + attn residual
__device__ float g_hn[NMAX * D];       // LayerNorm(h)
__device__ float g_act[NMAX * 2 * D];  // gelu(hn@W1+b1)
__device__ int   g_cnt[NMAX];          // per-dst degree
__device__ int   g_off[NMAX + 1];      // exclusive prefix
__device__ int   g_cur[NMAX];          // scatter cursors
__device__ int   g_srt[EMAX];          // src ids sorted by dst
__device__ int   g_bsum[128];          // scan block sums

// ---------------- sort phase ----------------
__global__ void k_zero(int n) {
    int i = blockIdx.x * blockDim.x + threadIdx.x;
    if (i < n) g_cnt[i] = 0;
}

__global__ void k_hist(const int* __restrict__ ei, int E) {
    int e = blockIdx.x * blockDim.x + threadIdx.x;
    if (e < E) atomicAdd(&g_cnt[__ldg(ei + E + e)], 1);
}

// pass 1: per-block (1024) exclusive scan + block sum
__global__ __launch_bounds__(1024)
void k_scan1(int n) {
    __shared__ int ws[32];
    const int tid = threadIdx.x, lane = tid & 31, w = tid >> 5;
    int i = blockIdx.x * 1024 + tid;
    int v = (i < n) ? g_cnt[i] : 0;
    int x = v;
#pragma unroll
    for (int o = 1; o < 32; o <<= 1) {
        int y = __shfl_up_sync(~0u, x, o);
        if (lane >= o) x += y;
    }
    if (lane == 31) ws[w] = x;
    __syncthreads();
    if (w == 0) {
        int s = ws[lane];
#pragma unroll
        for (int o = 1; o < 32; o <<= 1) {
            int y = __shfl_up_sync(~0u, s, o);
            if (lane >= o) s += y;
        }
        ws[lane] = s;
    }
    __syncthreads();
    int incl = x + (w > 0 ? ws[w - 1] : 0);
    if (i < n) g_off[i] = incl - v;
    if (tid == 1023) g_bsum[blockIdx.x] = incl;
}

// pass 2: exclusive scan of <=128 block sums, one block
__global__ void k_scan2(int nb) {
    __shared__ int ws[4];
    const int tid = threadIdx.x, lane = tid & 31, w = tid >> 5;
    int v = (tid < nb) ? g_bsum[tid] : 0;
    int x = v;
#pragma unroll
    for (int o = 1; o < 32; o <<= 1) {
        int y = __shfl_up_sync(~0u, x, o);
        if (lane >= o) x += y;
    }
    if (lane == 31) ws[w] = x;
    __syncthreads();
    if (tid == 0) { int a = 0; for (int k = 0; k < 4; ++k) { int t = ws[k]; ws[k] = a; a += t; } }
    __syncthreads();
    g_bsum[tid] = x - v + ws[w];
}

// pass 3: add block offsets, copy cursors, set sentinel
__global__ void k_scan3(int n, int E) {
    int i = blockIdx.x * blockDim.x + threadIdx.x;
    if (i < n) {
        int o = g_off[i] + g_bsum[i >> 10];
        g_off[i] = o;
        g_cur[i] = o;
    }
    if (i == 0) g_off[n] = E;
}

__global__ void k_scatter(const int* __restrict__ ei, int E) {
    int e = blockIdx.x * blockDim.x + threadIdx.x;
    if (e >= E) return;
    int src = __ldg(ei + e);
    int dst = __ldg(ei + E + e);
    int pos = atomicAdd(&g_cur[dst], 1);
    g_srt[pos] = src;
}

// ---------------- mma helpers ----------------
__device__ __forceinline__ void mma_tf32(float c[4],
    float a0, float a1, float a2, float a3, float b0, float b1)
{
    asm volatile(
        "mma.sync.aligned.m16n8k8.row.col.f32.tf32.tf32.f32 "
        "{%0,%1,%2,%3}, {%4,%5,%6,%7}, {%8,%9}, {%0,%1,%2,%3};"
        : "+f"(c[0]), "+f"(c[1]), "+f"(c[2]), "+f"(c[3])
        : "r"(__float_as_uint(a0)), "r"(__float_as_uint(a1)),
          "r"(__float_as_uint(a2)), "r"(__float_as_uint(a3)),
          "r"(__float_as_uint(b0)), "r"(__float_as_uint(b1)));
}

__device__ __forceinline__ void cpa16(void* smem_dst, const void* gsrc, int sz) {
    unsigned s = (unsigned)__cvta_generic_to_shared(smem_dst);
    asm volatile("cp.async.cg.shared.global [%0], [%1], 16, %2;"
                 :: "r"(s), "l"(gsrc), "r"(sz));
}

#define SMEM_GEMM_BYTES ((2 * 128 * 36 + 2 * 32 * 136) * 4)

// ---------------- double-buffered tf32 tensor-core GEMM body ----------------
// EPI: 0 = fp32 +bias ; 1 = fp32 gelu(+bias) ; 2 = fp32 +bias+R ; 3 = bf16 +bias
template <int KA, int EPI>
__device__ __forceinline__ void gemm_body(
    const float* __restrict__ A, const float* __restrict__ B,
    const float* __restrict__ bias, const float* __restrict__ R,
    void* __restrict__ Cv, int nrows, int ncols, int n0)
{
    extern __shared__ float sm[];
    float* As = sm;                    // [2][128][36]
    float* Bs = sm + 2 * 128 * 36;     // [2][32][136]
#define AS(b, r, c) As[(b) * (128 * 36) + (r) * 36 + (c)]
#define BS(b, r, c) Bs[(b) * (32 * 136) + (r) * 136 + (c)]

    const int tid  = threadIdx.x;
    const int m0   = blockIdx.x * 128;
    const int w    = tid >> 5;
    const int lane = tid & 31;
    const int g    = lane >> 2;
    const int tig  = lane & 3;
    const int wm   = (w >> 2) * 64;
    const int wn   = (w & 3) * 32;

    float acc[4][4][4];
#pragma unroll
    for (int i = 0; i < 4; ++i)
#pragma unroll
        for (int j = 0; j < 4; ++j)
#pragma unroll
            for (int q = 0; q < 4; ++q) acc[i][j][q] = 0.0f;

    const int arow = tid >> 3;          // 0..31 (+32p)
    const int acol = (tid & 7) << 2;    // 0..28
    const int brow = tid >> 5;          // 0..7 (+8p)
    const int bcol = (tid & 31) << 2;   // 0..124

    auto load_tiles = [&](int buf, int kc) {
#pragma unroll
        for (int p = 0; p < 4; ++p) {
            int r = arow + (p << 5);
            int sz = (m0 + r < nrows) ? 16 : 0;
            cpa16(&AS(buf, r, acol), A + (size_t)(m0 + r) * KA + kc + acol, sz);
        }
#pragma unroll
        for (int p = 0; p < 4; ++p) {
            int r = brow + (p << 3);
            cpa16(&BS(buf, r, bcol), B + (size_t)(kc + r) * ncols + n0 + bcol, 16);
        }
    };

    constexpr int NCH = KA / 32;
    load_tiles(0, 0);
    asm volatile("cp.async.commit_group;");

#pragma unroll 1
    for (int c = 0; c < NCH; ++c) {
        if (c + 1 < NCH) {
            load_tiles((c + 1) & 1, (c + 1) * 32);
            asm volatile("cp.async.commit_group;");
            asm volatile("cp.async.wait_group 1;");
        } else {
            asm volatile("cp.async.wait_group 0;");
        }
        __syncthreads();

        const int buf = c & 1;
#pragma unroll
        for (int ks = 0; ks < 4; ++ks) {
            const int kk = ks * 8;
            float af[4][4];
#pragma unroll
            for (int ms = 0; ms < 4; ++ms) {
                int row = wm + ms * 16 + g;
                af[ms][0] = AS(buf, row,     kk + tig);
                af[ms][1] = AS(buf, row + 8, kk + tig);
                af[ms][2] = AS(buf, row,     kk + tig + 4);
                af[ms][3] = AS(buf, row + 8, kk + tig + 4);
            }
            float bf[4][2];
#pragma unroll
            for (int ns = 0; ns < 4; ++ns) {
                int col = wn + ns * 8 + g;
                bf[ns][0] = BS(buf, kk + tig,     col);
                bf[ns][1] = BS(buf, kk + tig + 4, col);
            }
#pragma unroll
            for (int ms = 0; ms < 4; ++ms)
#pragma unroll
                for (int ns = 0; ns < 4; ++ns)
                    mma_tf32(acc[ms][ns], af[ms][0], af[ms][1], af[ms][2], af[ms][3],
                             bf[ns][0], bf[ns][1]);
        }
        __syncthreads();
    }

    // ---- epilogue ----
#pragma unroll
    for (int ms = 0; ms < 4; ++ms) {
        int row0 = m0 + wm + ms * 16 + g;
#pragma unroll
        for (int half = 0; half < 2; ++half) {
            int row = row0 + half * 8;
            if (row >= nrows) continue;
#pragma unroll
            for (int ns = 0; ns < 4; ++ns) {
                int col = n0 + wn + ns * 8 + tig * 2;
                float v0 = acc[ms][ns][half * 2 + 0] + __ldg(bias + col);
                float v1 = acc[ms][ns][half * 2 + 1] + __ldg(bias + col + 1);
                if (EPI == 1) {
                    v0 = 0.5f * v0 * (1.0f + erff(v0 * 0.70710678118654752f));
                    v1 = 0.5f * v1 * (1.0f + erff(v1 * 0.70710678118654752f));
                } else if (EPI == 2) {
                    const float2 r2 = *(const float2*)(R + (size_t)row * ncols + col);
                    v0 += r2.x; v1 += r2.y;
                }
                if (EPI == 3) {
                    __nv_bfloat162 p = __floats2bfloat162_rn(v0, v1);
                    *(__nv_bfloat162*)((__nv_bfloat16*)Cv + (size_t)row * ncols + col) = p;
                } else {
                    *(float2*)((float*)Cv + (size_t)row * ncols + col) = make_float2(v0, v1);
                }
            }
        }
    }
#undef AS
#undef BS
}

template <int KA, int EPI>
__global__ __launch_bounds__(256)
void k_gemm_tc(const float* __restrict__ A, const float* __restrict__ B,
               const float* __restrict__ bias, const float* __restrict__ R,
               void* __restrict__ C, int nrows, int ncols)
{
    gemm_body<KA, EPI>(A, B, bias, R, C, nrows, ncols, blockIdx.y * 128);
}

__global__ __launch_bounds__(256)
void k_gemm_qkv(const float* __restrict__ A,
                const float* __restrict__ Bq, const float* __restrict__ Bk,
                const float* __restrict__ Bv,
                const float* __restrict__ bq, const float* __restrict__ bk,
                const float* __restrict__ bv, int nrows)
{
    if (blockIdx.z == 0)
        gemm_body<128, 0>(A, Bq, bq, nullptr, g_Q, nrows, 128, 0);
    else if (blockIdx.z == 1)
        gemm_body<128, 3>(A, Bk, bk, nullptr, g_Kh, nrows, 128, 0);
    else
        gemm_body<128, 3>(A, Bv, bv, nullptr, g_Vh, nrows, 128, 0);
}

// ---------------- fused attention + residual + LayerNorm, warp per dst ----------------
__device__ __forceinline__ float2 bf2f(unsigned u) {
    __nv_bfloat162 h = *reinterpret_cast<__nv_bfloat162*>(&u);
    return __bfloat1622float2(h);
}

__global__ __launch_bounds__(256)
void k_attn(const float* __restrict__ x,
            const float* __restrict__ lng, const float* __restrict__ lnb, int n)
{
    int row = (blockIdx.x * blockDim.x + threadIdx.x) >> 5;
    if (row >= n) return;
    const int lane = threadIdx.x & 31;
    const size_t lo = (size_t)lane * 4;

    float4 q = *(const float4*)(g_Q + (size_t)row * D + lo);
    float ax = 0.f, ay = 0.f, az = 0.f, aw = 0.f, den = 0.f;

    int beg = g_off[row], end = g_off[row + 1];
    int j = beg;
    for (; j + 1 < end; j += 2) {
        int s0 = g_srt[j], s1 = g_srt[j + 1];
        uint2 kr0 = *(const uint2*)(g_Kh + (size_t)s0 * D + lo);
        uint2 kr1 = *(const uint2*)(g_Kh + (size_t)s1 * D + lo);
        uint2 vr0 = *(const uint2*)(g_Vh + (size_t)s0 * D + lo);
        uint2 vr1 = *(const uint2*)(g_Vh + (size_t)s1 * D + lo);
        float2 ka = bf2f(kr0.x), kb = bf2f(kr0.y);
        float2 kc = bf2f(kr1.x), kd = bf2f(kr1.y);
        float d0 = q.x * ka.x + q.y * ka.y + q.z * kb.x + q.w * kb.y;
        float d1 = q.x * kc.x + q.y * kc.y + q.z * kd.x + q.w * kd.y;
        d0 += __shfl_xor_sync(~0u, d0, 1);
        d1 += __shfl_xor_sync(~0u, d1, 1);
        d0 += __shfl_xor_sync(~0u, d0, 2);
        d1 += __shfl_xor_sync(~0u, d1, 2);
        float ex0 = __expf(d0 * 0.25f);
        float ex1 = __expf(d1 * 0.25f);
        den += ex0 + ex1;
        float2 va = bf2f(vr0.x), vb = bf2f(vr0.y);
        float2 vc = bf2f(vr1.x), vd = bf2f(vr1.y);
        ax += ex0 * va.x + ex1 * vc.x;
        ay += ex0 * va.y + ex1 * vc.y;
        az += ex0 * vb.x + ex1 * vd.x;
        aw += ex0 * vb.y + ex1 * vd.y;
    }
    if (j < end) {
        int s0 = g_srt[j];
        uint2 kr0 = *(const uint2*)(g_Kh + (size_t)s0 * D + lo);
        uint2 vr0 = *(const uint2*)(g_Vh + (size_t)s0 * D + lo);
        float2 ka = bf2f(kr0.x), kb = bf2f(kr0.y);
        float d0 = q.x * ka.x + q.y * ka.y + q.z * kb.x + q.w * kb.y;
        d0 += __shfl_xor_sync(~0u, d0, 1);
        d0 += __shfl_xor_sync(~0u, d0, 2);
        float ex0 = __expf(d0 * 0.25f);
        den += ex0;
        float2 va = bf2f(vr0.x), vb = bf2f(vr0.y);
        ax += ex0 * va.x; ay += ex0 * va.y;
        az += ex0 * vb.x; aw += ex0 * vb.y;
    }

    float inv = 1.0f / (den + 1e-16f);
    float4 xr = *(const float4*)(x + (size_t)row * D + lo);
    float4 hv = make_float4(xr.x + ax * inv, xr.y + ay * inv,
                            xr.z + az * inv, xr.w + aw * inv);
    *(float4*)(g_h + (size_t)row * D + lo) = hv;

    // fused LayerNorm
    float s = hv.x + hv.y + hv.z + hv.w;
#pragma unroll
    for (int o = 16; o > 0; o >>= 1) s += __shfl_xor_sync(~0u, s, o);
    float mu = s * (1.0f / 128.0f);
    float dx = hv.x - mu, dy = hv.y - mu, dz = hv.z - mu, dw = hv.w - mu;
    float vs = dx * dx + dy * dy + dz * dz + dw * dw;
#pragma unroll
    for (int o = 16; o > 0; o >>= 1) vs += __shfl_xor_sync(~0u, vs, o);
    float r = rsqrtf(vs * (1.0f / 128.0f) + 1e-5f);
    float4 gg = *(const float4*)(lng + lo);
    float4 bb = *(const float4*)(lnb + lo);
    float4 o;
    o.x = dx * r * gg.x + bb.x;
    o.y = dy * r * gg.y + bb.y;
    o.z = dz * r * gg.z + bb.z;
    o.w = dw * r * gg.w + bb.w;
    *(float4*)(g_hn + (size_t)row * D + lo) = o;
}

// ---------------- launch ----------------
extern "C" void kernel_launch(void* const* d_in, const int* in_sizes, int n_in,
                              void* d_out, int out_size) {
    const float* x    = (const float*)d_in[0];
    const int*   ei   = (const int*)  d_in[1];
    const float* Wq   = (const float*)d_in[2];
    const float* bq   = (const float*)d_in[3];
    const float* Wk   = (const float*)d_in[4];
    const float* bk   = (const float*)d_in[5];
    const float* Wv   = (const float*)d_in[6];
    const float* bv   = (const float*)d_in[7];
    const float* ln_g = (const float*)d_in[8];
    const float* ln_b = (const float*)d_in[9];
    const float* W1   = (const float*)d_in[10];
    const float* b1   = (const float*)d_in[11];
    const float* W2   = (const float*)d_in[12];
    const float* b2   = (const float*)d_in[13];
    float* out = (float*)d_out;

    const int n = in_sizes[0] / D;
    const int E = in_sizes[1] / 2;

    static float *phn = nullptr, *pact, *ph;
    if (!phn) {
        cudaGetSymbolAddress((void**)&phn,  g_hn);
        cudaGetSymbolAddress((void**)&pact, g_act);
        cudaGetSymbolAddress((void**)&ph,   g_h);
        cudaFuncSetAttribute(k_gemm_qkv,
            cudaFuncAttributeMaxDynamicSharedMemorySize, SMEM_GEMM_BYTES);
        cudaFuncSetAttribute(k_gemm_tc<128, 1>,
            cudaFuncAttributeMaxDynamicSharedMemorySize, SMEM_GEMM_BYTES);
        cudaFuncSetAttribute(k_gemm_tc<256, 2>,
            cudaFuncAttributeMaxDynamicSharedMemorySize, SMEM_GEMM_BYTES);
    }

    // --- counting sort of edges by dst ---
    const int nb = (n + 1023) / 1024;
    k_zero<<<(n + 255) / 256, 256>>>(n);
    k_hist<<<(E + 255) / 256, 256>>>(ei, E);
    k_scan1<<<nb, 1024>>>(n);
    k_scan2<<<1, 128>>>(nb);
    k_scan3<<<(n + 255) / 256, 256>>>(n, E);
    k_scatter<<<(E + 255) / 256, 256>>>(ei, E);

    // --- fused Q,K,V projections (tf32, cp.async double-buffered) ---
    dim3 gq((n + 127) / 128, 1, 3);
    k_gemm_qkv<<<gq, 256, SMEM_GEMM_BYTES>>>(x, Wq, Wk, Wv, bq, bk, bv, n);

    // --- fused attention + residual + LayerNorm ---
    k_attn<<<(n * 32 + 255) / 256, 256>>>(x, ln_g, ln_b, n);

    // --- FFN ---
    dim3 gf1((n + 127) / 128, 2);
    k_gemm_tc<128, 1><<<gf1, 256, SMEM_GEMM_BYTES>>>(phn, W1, b1, nullptr, pact, n, 2 * D);

    dim3 gf2((n + 127) / 128, 1);
    k_gemm_tc<256, 2><<<gf2, 256, SMEM_GEMM_BYTES>>>(pact, W2, b2, ph, out, n, D);
}

// round 5
// speedup vs baseline: 3.2221x; 1.0944x over previous
#include <cuda_runtime.h>
#include <cuda_bf16.h>
#include <math.h>

#define D     128
#define H     8
#define NMAX  50000
#define EMAX  800000

// ---------------- static device scratch ----------------
__device__ float g_Q[NMAX * D];
__device__ __nv_bfloat16 g_Kh[NMAX * D];
__device__ __nv_bfloat16 g_Vh[NMAX * D];
__device__ float g_h[NMAX * D];               // h = x + attn residual (fp32, FFN2 residual)
__device__ __nv_bfloat16 g_hnh[NMAX * D];     // LayerNorm(h) in bf16 (FFN1 A input)
__device__ __nv_bfloat16 g_acth[NMAX * 2 * D];// gelu(hn@W1+b1) bf16 (FFN2 A input)
__device__ __nv_bfloat16 g_W1t[2 * D * D];    // W1^T bf16 [256][128]
__device__ __nv_bfloat16 g_W2t[2 * D * D];    // W2^T bf16 [128][256]
__device__ int   g_cnt[NMAX];                 // per-dst degree (zeroed by scan1 for next replay)
__device__ int   g_off[NMAX + 1];             // exclusive prefix
__device__ int   g_cur[NMAX];                 // scatter cursors
__device__ int   g_srt[EMAX];                 // src ids sorted by dst
__device__ int   g_bsum[128];                 // scan block sums

// ---------------- sort phase ----------------
__global__ void k_hist(const int* __restrict__ ei, int E) {
    int e = blockIdx.x * blockDim.x + threadIdx.x;
    if (e < E) atomicAdd(&g_cnt[__ldg(ei + E + e)], 1);
}

// per-block (1024) exclusive scan + block sum; zeroes g_cnt for the next replay
__global__ __launch_bounds__(1024)
void k_scan1(int n) {
    __shared__ int ws[32];
    const int tid = threadIdx.x, lane = tid & 31, w = tid >> 5;
    int i = blockIdx.x * 1024 + tid;
    int v = 0;
    if (i < n) { v = g_cnt[i]; g_cnt[i] = 0; }
    int x = v;
#pragma unroll
    for (int o = 1; o < 32; o <<= 1) {
        int y = __shfl_up_sync(~0u, x, o);
        if (lane >= o) x += y;
    }
    if (lane == 31) ws[w] = x;
    __syncthreads();
    if (w == 0) {
        int s = ws[lane];
#pragma unroll
        for (int o = 1; o < 32; o <<= 1) {
            int y = __shfl_up_sync(~0u, s, o);
            if (lane >= o) s += y;
        }
        ws[lane] = s;
    }
    __syncthreads();
    int incl = x + (w > 0 ? ws[w - 1] : 0);
    if (i < n) g_off[i] = incl - v;
    if (tid == 1023) g_bsum[blockIdx.x] = incl;
}

// add block-prefix (each block reduces bsums itself), copy cursors, sentinel
__global__ __launch_bounds__(1024)
void k_scan3(int n, int E) {
    __shared__ int s_base;
    const int j = blockIdx.x;
    if (threadIdx.x < 32) {
        int acc = 0;
        for (int t = threadIdx.x; t < j; t += 32) acc += g_bsum[t];
#pragma unroll
        for (int o = 16; o > 0; o >>= 1) acc += __shfl_xor_sync(~0u, acc, o);
        if (threadIdx.x == 0) s_base = acc;
    }
    __syncthreads();
    int i = j * 1024 + threadIdx.x;
    if (i < n) {
        int o = g_off[i] + s_base;
        g_off[i] = o;
        g_cur[i] = o;
    }
    if (i == 0) g_off[n] = E;
}

__global__ void k_scatter(const int* __restrict__ ei, int E) {
    int e = blockIdx.x * blockDim.x + threadIdx.x;
    if (e >= E) return;
    int src = __ldg(ei + e);
    int dst = __ldg(ei + E + e);
    int pos = atomicAdd(&g_cur[dst], 1);
    g_srt[pos] = src;
}

// ---------------- weight conversion: W1[128][256]->W1t bf16[256][128]; W2[256][128]->W2t[128][256] ----------------
__global__ void k_convw(const float* __restrict__ W1, const float* __restrict__ W2) {
    int i = blockIdx.x * blockDim.x + threadIdx.x;   // 0 .. 32767
    if (i < 128 * 256) {
        int k = i >> 8, nn = i & 255;
        g_W1t[nn * 128 + k] = __float2bfloat16(W1[i]);
    }
    {
        int k = i >> 7, nn = i & 127;
        g_W2t[nn * 256 + k] = __float2bfloat16(W2[i]);
    }
}

// ---------------- mma helpers ----------------
__device__ __forceinline__ void mma_tf32(float c[4],
    float a0, float a1, float a2, float a3, float b0, float b1)
{
    asm volatile(
        "mma.sync.aligned.m16n8k8.row.col.f32.tf32.tf32.f32 "
        "{%0,%1,%2,%3}, {%4,%5,%6,%7}, {%8,%9}, {%0,%1,%2,%3};"
        : "+f"(c[0]), "+f"(c[1]), "+f"(c[2]), "+f"(c[3])
        : "r"(__float_as_uint(a0)), "r"(__float_as_uint(a1)),
          "r"(__float_as_uint(a2)), "r"(__float_as_uint(a3)),
          "r"(__float_as_uint(b0)), "r"(__float_as_uint(b1)));
}

__device__ __forceinline__ void mma_bf16(float c[4],
    unsigned a0, unsigned a1, unsigned a2, unsigned a3,
    unsigned b0, unsigned b1)
{
    asm volatile(
        "mma.sync.aligned.m16n8k16.row.col.f32.bf16.bf16.f32 "
        "{%0,%1,%2,%3}, {%4,%5,%6,%7}, {%8,%9}, {%0,%1,%2,%3};"
        : "+f"(c[0]), "+f"(c[1]), "+f"(c[2]), "+f"(c[3])
        : "r"(a0), "r"(a1), "r"(a2), "r"(a3), "r"(b0), "r"(b1));
}

__device__ __forceinline__ void cpa16(void* smem_dst, const void* gsrc, int sz) {
    unsigned s = (unsigned)__cvta_generic_to_shared(smem_dst);
    asm volatile("cp.async.cg.shared.global [%0], [%1], 16, %2;"
                 :: "r"(s), "l"(gsrc), "r"(sz));
}

#define SMEM_TF32_BYTES ((2 * 128 * 36 + 2 * 32 * 136) * 4)
#define SMEM_BF16_BYTES (2 * (2 * 128 * 40) * 2)

// ---------------- tf32 double-buffered GEMM (QKV) ----------------
// EPI: 0 = fp32 +bias ; 3 = bf16 +bias
template <int KA, int EPI>
__device__ __forceinline__ void gemm_body(
    const float* __restrict__ A, const float* __restrict__ B,
    const float* __restrict__ bias,
    void* __restrict__ Cv, int nrows, int ncols, int n0)
{
    extern __shared__ float sm[];
    float* As = sm;                    // [2][128][36]
    float* Bs = sm + 2 * 128 * 36;     // [2][32][136]
#define AS(b, r, c) As[(b) * (128 * 36) + (r) * 36 + (c)]
#define BS(b, r, c) Bs[(b) * (32 * 136) + (r) * 136 + (c)]

    const int tid  = threadIdx.x;
    const int m0   = blockIdx.x * 128;
    const int w    = tid >> 5;
    const int lane = tid & 31;
    const int g    = lane >> 2;
    const int tig  = lane & 3;
    const int wm   = (w >> 2) * 64;
    const int wn   = (w & 3) * 32;

    float acc[4][4][4];
#pragma unroll
    for (int i = 0; i < 4; ++i)
#pragma unroll
        for (int j = 0; j < 4; ++j)
#pragma unroll
            for (int q = 0; q < 4; ++q) acc[i][j][q] = 0.0f;

    const int arow = tid >> 3;
    const int acol = (tid & 7) << 2;
    const int brow = tid >> 5;
    const int bcol = (tid & 31) << 2;

    auto load_tiles = [&](int buf, int kc) {
#pragma unroll
        for (int p = 0; p < 4; ++p) {
            int r = arow + (p << 5);
            int sz = (m0 + r < nrows) ? 16 : 0;
            cpa16(&AS(buf, r, acol), A + (size_t)(m0 + r) * KA + kc + acol, sz);
        }
#pragma unroll
        for (int p = 0; p < 4; ++p) {
            int r = brow + (p << 3);
            cpa16(&BS(buf, r, bcol), B + (size_t)(kc + r) * ncols + n0 + bcol, 16);
        }
    };

    constexpr int NCH = KA / 32;
    load_tiles(0, 0);
    asm volatile("cp.async.commit_group;");

#pragma unroll 1
    for (int c = 0; c < NCH; ++c) {
        if (c + 1 < NCH) {
            load_tiles((c + 1) & 1, (c + 1) * 32);
            asm volatile("cp.async.commit_group;");
            asm volatile("cp.async.wait_group 1;");
        } else {
            asm volatile("cp.async.wait_group 0;");
        }
        __syncthreads();

        const int buf = c & 1;
#pragma unroll
        for (int ks = 0; ks < 4; ++ks) {
            const int kk = ks * 8;
            float af[4][4];
#pragma unroll
            for (int ms = 0; ms < 4; ++ms) {
                int row = wm + ms * 16 + g;
                af[ms][0] = AS(buf, row,     kk + tig);
                af[ms][1] = AS(buf, row + 8, kk + tig);
                af[ms][2] = AS(buf, row,     kk + tig + 4);
                af[ms][3] = AS(buf, row + 8, kk + tig + 4);
            }
            float bf[4][2];
#pragma unroll
            for (int ns = 0; ns < 4; ++ns) {
                int col = wn + ns * 8 + g;
                bf[ns][0] = BS(buf, kk + tig,     col);
                bf[ns][1] = BS(buf, kk + tig + 4, col);
            }
#pragma unroll
            for (int ms = 0; ms < 4; ++ms)
#pragma unroll
                for (int ns = 0; ns < 4; ++ns)
                    mma_tf32(acc[ms][ns], af[ms][0], af[ms][1], af[ms][2], af[ms][3],
                             bf[ns][0], bf[ns][1]);
        }
        __syncthreads();
    }

#pragma unroll
    for (int ms = 0; ms < 4; ++ms) {
        int row0 = m0 + wm + ms * 16 + g;
#pragma unroll
        for (int half = 0; half < 2; ++half) {
            int row = row0 + half * 8;
            if (row >= nrows) continue;
#pragma unroll
            for (int ns = 0; ns < 4; ++ns) {
                int col = n0 + wn + ns * 8 + tig * 2;
                float v0 = acc[ms][ns][half * 2 + 0] + __ldg(bias + col);
                float v1 = acc[ms][ns][half * 2 + 1] + __ldg(bias + col + 1);
                if (EPI == 3) {
                    __nv_bfloat162 p = __floats2bfloat162_rn(v0, v1);
                    *(__nv_bfloat162*)((__nv_bfloat16*)Cv + (size_t)row * ncols + col) = p;
                } else {
                    *(float2*)((float*)Cv + (size_t)row * ncols + col) = make_float2(v0, v1);
                }
            }
        }
    }
#undef AS
#undef BS
}

__global__ __launch_bounds__(256)
void k_gemm_qkv(const float* __restrict__ A,
                const float* __restrict__ Bq, const float* __restrict__ Bk,
                const float* __restrict__ Bv,
                const float* __restrict__ bq, const float* __restrict__ bk,
                const float* __restrict__ bv, int nrows)
{
    if (blockIdx.z == 0)
        gemm_body<128, 0>(A, Bq, bq, g_Q, nrows, 128, 0);
    else if (blockIdx.z == 1)
        gemm_body<128, 3>(A, Bk, bk, g_Kh, nrows, 128, 0);
    else
        gemm_body<128, 3>(A, Bv, bv, g_Vh, nrows, 128, 0);
}

// ---------------- bf16 double-buffered GEMM (FFN) ----------------
// A bf16 [nrows][KA] row-major; Bt bf16 [ncols][KA] row-major (n-major!).
// EPI: 1 = gelu(+bias) -> bf16 out ; 2 = +bias + R(fp32) -> fp32 out
template <int KA, int EPI>
__global__ __launch_bounds__(256)
void k_gemm_bf(const __nv_bfloat16* __restrict__ A, const __nv_bfloat16* __restrict__ Bt,
               const float* __restrict__ bias, const float* __restrict__ R,
               void* __restrict__ Cv, int nrows, int ncols)
{
    extern __shared__ __nv_bfloat16 smh[];
    // As[2][128][40], Bs[2][128][40]  (k-chunk 32, pad to 40 halves/row)
#define SA(b, r, c) smh[(b) * (128 * 40) + (r) * 40 + (c)]
#define SB(b, r, c) smh[2 * 128 * 40 + (b) * (128 * 40) + (r) * 40 + (c)]

    const int tid  = threadIdx.x;
    const int m0   = blockIdx.x * 128;
    const int n0   = blockIdx.y * 128;
    const int w    = tid >> 5;
    const int lane = tid & 31;
    const int g    = lane >> 2;
    const int tig  = lane & 3;
    const int wm   = (w >> 2) * 64;
    const int wn   = (w & 3) * 32;

    float acc[4][4][4];
#pragma unroll
    for (int i = 0; i < 4; ++i)
#pragma unroll
        for (int j = 0; j < 4; ++j)
#pragma unroll
            for (int q = 0; q < 4; ++q) acc[i][j][q] = 0.0f;

    auto load_tiles = [&](int buf, int kc) {
#pragma unroll
        for (int p = 0; p < 2; ++p) {
            int seg = tid + p * 256;
            int r = seg >> 2, ko = (seg & 3) << 3;
            int sz = (m0 + r < nrows) ? 16 : 0;
            cpa16(&SA(buf, r, ko), A + (size_t)(m0 + r) * KA + kc + ko, sz);
        }
#pragma unroll
        for (int p = 0; p < 2; ++p) {
            int seg = tid + p * 256;
            int r = seg >> 2, ko = (seg & 3) << 3;
            cpa16(&SB(buf, r, ko), Bt + (size_t)(n0 + r) * KA + kc + ko, 16);
        }
    };

    constexpr int NCH = KA / 32;
    load_tiles(0, 0);
    asm volatile("cp.async.commit_group;");

#pragma unroll 1
    for (int c = 0; c < NCH; ++c) {
        if (c + 1 < NCH) {
            load_tiles((c + 1) & 1, (c + 1) * 32);
            asm volatile("cp.async.commit_group;");
            asm volatile("cp.async.wait_group 1;");
        } else {
            asm volatile("cp.async.wait_group 0;");
        }
        __syncthreads();

        const int buf = c & 1;
#pragma unroll
        for (int ks = 0; ks < 2; ++ks) {
            const int kb = ks * 16 + 2 * tig;
            unsigned af[4][4];
#pragma unroll
            for (int ms = 0; ms < 4; ++ms) {
                int row = wm + ms * 16 + g;
                af[ms][0] = *(const unsigned*)&SA(buf, row,     kb);
                af[ms][1] = *(const unsigned*)&SA(buf, row + 8, kb);
                af[ms][2] = *(const unsigned*)&SA(buf, row,     kb + 8);
                af[ms][3] = *(const unsigned*)&SA(buf, row + 8, kb + 8);
            }
            unsigned bf[4][2];
#pragma unroll
            for (int ns = 0; ns < 4; ++ns) {
                int col = wn + ns * 8 + g;
                bf[ns][0] = *(const unsigned*)&SB(buf, col, kb);
                bf[ns][1] = *(const unsigned*)&SB(buf, col, kb + 8);
            }
#pragma unroll
            for (int ms = 0; ms < 4; ++ms)
#pragma unroll
                for (int ns = 0; ns < 4; ++ns)
                    mma_bf16(acc[ms][ns], af[ms][0], af[ms][1], af[ms][2], af[ms][3],
                             bf[ns][0], bf[ns][1]);
        }
        __syncthreads();
    }

#pragma unroll
    for (int ms = 0; ms < 4; ++ms) {
        int row0 = m0 + wm + ms * 16 + g;
#pragma unroll
        for (int half = 0; half < 2; ++half) {
            int row = row0 + half * 8;
            if (row >= nrows) continue;
#pragma unroll
            for (int ns = 0; ns < 4; ++ns) {
                int col = n0 + wn + ns * 8 + tig * 2;
                float v0 = acc[ms][ns][half * 2 + 0] + __ldg(bias + col);
                float v1 = acc[ms][ns][half * 2 + 1] + __ldg(bias + col + 1);
                if (EPI == 1) {
                    v0 = 0.5f * v0 * (1.0f + erff(v0 * 0.70710678118654752f));
                    v1 = 0.5f * v1 * (1.0f + erff(v1 * 0.70710678118654752f));
                    __nv_bfloat162 p = __floats2bfloat162_rn(v0, v1);
                    *(__nv_bfloat162*)((__nv_bfloat16*)Cv + (size_t)row * ncols + col) = p;
                } else {
                    const float2 r2 = *(const float2*)(R + (size_t)row * ncols + col);
                    *(float2*)((float*)Cv + (size_t)row * ncols + col) =
                        make_float2(v0 + r2.x, v1 + r2.y);
                }
            }
        }
    }
#undef SA
#undef SB
}

// ---------------- fused attention + residual + LayerNorm, warp per dst ----------------
__device__ __forceinline__ float2 bf2f(unsigned u) {
    __nv_bfloat162 h = *reinterpret_cast<__nv_bfloat162*>(&u);
    return __bfloat1622float2(h);
}

__global__ __launch_bounds__(256)
void k_attn(const float* __restrict__ x,
            const float* __restrict__ lng, const float* __restrict__ lnb, int n)
{
    int row = (blockIdx.x * blockDim.x + threadIdx.x) >> 5;
    if (row >= n) return;
    const int lane = threadIdx.x & 31;
    const size_t lo = (size_t)lane * 4;

    float4 q = *(const float4*)(g_Q + (size_t)row * D + lo);
    float ax = 0.f, ay = 0.f, az = 0.f, aw = 0.f, den = 0.f;

    int beg = g_off[row], end = g_off[row + 1];
    int j = beg;
    for (; j + 1 < end; j += 2) {
        int s0 = g_srt[j], s1 = g_srt[j + 1];
        uint2 kr0 = *(const uint2*)(g_Kh + (size_t)s0 * D + lo);
        uint2 kr1 = *(const uint2*)(g_Kh + (size_t)s1 * D + lo);
        uint2 vr0 = *(const uint2*)(g_Vh + (size_t)s0 * D + lo);
        uint2 vr1 = *(const uint2*)(g_Vh + (size_t)s1 * D + lo);
        float2 ka = bf2f(kr0.x), kb = bf2f(kr0.y);
        float2 kc = bf2f(kr1.x), kd = bf2f(kr1.y);
        float d0 = q.x * ka.x + q.y * ka.y + q.z * kb.x + q.w * kb.y;
        float d1 = q.x * kc.x + q.y * kc.y + q.z * kd.x + q.w * kd.y;
        d0 += __shfl_xor_sync(~0u, d0, 1);
        d1 += __shfl_xor_sync(~0u, d1, 1);
        d0 += __shfl_xor_sync(~0u, d0, 2);
        d1 += __shfl_xor_sync(~0u, d1, 2);
        float ex0 = __expf(d0 * 0.25f);
        float ex1 = __expf(d1 * 0.25f);
        den += ex0 + ex1;
        float2 va = bf2f(vr0.x), vb = bf2f(vr0.y);
        float2 vc = bf2f(vr1.x), vd = bf2f(vr1.y);
        ax += ex0 * va.x + ex1 * vc.x;
        ay += ex0 * va.y + ex1 * vc.y;
        az += ex0 * vb.x + ex1 * vd.x;
        aw += ex0 * vb.y + ex1 * vd.y;
    }
    if (j < end) {
        int s0 = g_srt[j];
        uint2 kr0 = *(const uint2*)(g_Kh + (size_t)s0 * D + lo);
        uint2 vr0 = *(const uint2*)(g_Vh + (size_t)s0 * D + lo);
        float2 ka = bf2f(kr0.x), kb = bf2f(kr0.y);
        float d0 = q.x * ka.x + q.y * ka.y + q.z * kb.x + q.w * kb.y;
        d0 += __shfl_xor_sync(~0u, d0, 1);
        d0 += __shfl_xor_sync(~0u, d0, 2);
        float ex0 = __expf(d0 * 0.25f);
        den += ex0;
        float2 va = bf2f(vr0.x), vb = bf2f(vr0.y);
        ax += ex0 * va.x; ay += ex0 * va.y;
        az += ex0 * vb.x; aw += ex0 * vb.y;
    }

    float inv = 1.0f / (den + 1e-16f);
    float4 xr = *(const float4*)(x + (size_t)row * D + lo);
    float4 hv = make_float4(xr.x + ax * inv, xr.y + ay * inv,
                            xr.z + az * inv, xr.w + aw * inv);
    *(float4*)(g_h + (size_t)row * D + lo) = hv;

    // fused LayerNorm -> bf16
    float s = hv.x + hv.y + hv.z + hv.w;
#pragma unroll
    for (int o = 16; o > 0; o >>= 1) s += __shfl_xor_sync(~0u, s, o);
    float mu = s * (1.0f / 128.0f);
    float dx = hv.x - mu, dy = hv.y - mu, dz = hv.z - mu, dw = hv.w - mu;
    float vs = dx * dx + dy * dy + dz * dz + dw * dw;
#pragma unroll
    for (int o = 16; o > 0; o >>= 1) vs += __shfl_xor_sync(~0u, vs, o);
    float r = rsqrtf(vs * (1.0f / 128.0f) + 1e-5f);
    float4 gg = *(const float4*)(lng + lo);
    float4 bb = *(const float4*)(lnb + lo);
    __nv_bfloat162 o0 = __floats2bfloat162_rn(dx * r * gg.x + bb.x, dy * r * gg.y + bb.y);
    __nv_bfloat162 o1 = __floats2bfloat162_rn(dz * r * gg.z + bb.z, dw * r * gg.w + bb.w);
    *(__nv_bfloat162*)(g_hnh + (size_t)row * D + lo)     = o0;
    *(__nv_bfloat162*)(g_hnh + (size_t)row * D + lo + 2) = o1;
}

// ---------------- launch ----------------
extern "C" void kernel_launch(void* const* d_in, const int* in_sizes, int n_in,
                              void* d_out, int out_size) {
    const float* x    = (const float*)d_in[0];
    const int*   ei   = (const int*)  d_in[1];
    const float* Wq   = (const float*)d_in[2];
    const float* bq   = (const float*)d_in[3];
    const float* Wk   = (const float*)d_in[4];
    const float* bk   = (const float*)d_in[5];
    const float* Wv   = (const float*)d_in[6];
    const float* bv   = (const float*)d_in[7];
    const float* ln_g = (const float*)d_in[8];
    const float* ln_b = (const float*)d_in[9];
    const float* W1   = (const float*)d_in[10];
    const float* b1   = (const float*)d_in[11];
    const float* W2   = (const float*)d_in[12];
    const float* b2   = (const float*)d_in[13];
    float* out = (float*)d_out;

    const int n = in_sizes[0] / D;
    const int E = in_sizes[1] / 2;

    static bool inited = false;
    static __nv_bfloat16 *phn, *pact, *pW1t, *pW2t;
    static float *ph;
    static cudaStream_t s1, s2;
    static cudaEvent_t evFork, evSort, evW;
    if (!inited) {
        cudaGetSymbolAddress((void**)&phn,  g_hnh);
        cudaGetSymbolAddress((void**)&pact, g_acth);
        cudaGetSymbolAddress((void**)&pW1t, g_W1t);
        cudaGetSymbolAddress((void**)&pW2t, g_W2t);
        cudaGetSymbolAddress((void**)&ph,   g_h);
        cudaFuncSetAttribute(k_gemm_qkv,
            cudaFuncAttributeMaxDynamicSharedMemorySize, SMEM_TF32_BYTES);
        cudaStreamCreateWithFlags(&s1, cudaStreamNonBlocking);
        cudaStreamCreateWithFlags(&s2, cudaStreamNonBlocking);
        cudaEventCreateWithFlags(&evFork, cudaEventDisableTiming);
        cudaEventCreateWithFlags(&evSort, cudaEventDisableTiming);
        cudaEventCreateWithFlags(&evW,    cudaEventDisableTiming);
        inited = true;
    }

    // fork side streams off the main (captured) stream
    cudaEventRecord(evFork, 0);
    cudaStreamWaitEvent(s1, evFork, 0);
    cudaStreamWaitEvent(s2, evFork, 0);

    // --- side stream 1: counting sort of edges by dst ---
    const int nb = (n + 1023) / 1024;
    k_hist<<<(E + 255) / 256, 256, 0, s1>>>(ei, E);
    k_scan1<<<nb, 1024, 0, s1>>>(n);
    k_scan3<<<nb, 1024, 0, s1>>>(n, E);
    k_scatter<<<(E + 255) / 256, 256, 0, s1>>>(ei, E);
    cudaEventRecord(evSort, s1);

    // --- side stream 2: FFN weight conversion (fp32 -> bf16, transposed) ---
    k_convw<<<128, 256, 0, s2>>>(W1, W2);
    cudaEventRecord(evW, s2);

    // --- main: fused Q,K,V projections (tf32, cp.async double-buffered) ---
    dim3 gq((n + 127) / 128, 1, 3);
    k_gemm_qkv<<<gq, 256, SMEM_TF32_BYTES>>>(x, Wq, Wk, Wv, bq, bk, bv, n);

    // join sort, run fused attention + residual + LayerNorm
    cudaStreamWaitEvent(0, evSort, 0);
    k_attn<<<(n * 32 + 255) / 256, 256>>>(x, ln_g, ln_b, n);

    // join weights, FFN (bf16 mma)
    cudaStreamWaitEvent(0, evW, 0);
    dim3 gf1((n + 127) / 128, 2);
    k_gemm_bf<128, 1><<<gf1, 256, SMEM_BF16_BYTES>>>(phn, pW1t, b1, nullptr, pact, n, 2 * D);

    dim3 gf2((n + 127) / 128, 1);
    k_gemm_bf<256, 2><<<gf2, 256, SMEM_BF16_BYTES>>>(pact, pW2t, b2, ph, out, n, D);
}

// round 6
// speedup vs baseline: 3.3371x; 1.0357x over previous
#include <cuda_runtime.h>
#include <cuda_bf16.h>
#include <math.h>

#define D     128
#define H     8
#define NMAX  50000
#define EMAX  800000

// ---------------- static device scratch ----------------
__device__ float g_Q[NMAX * D];
__device__ __nv_bfloat16 g_xh[NMAX * D];      // x in bf16 (QKV A input)
__device__ __nv_bfloat16 g_Kh[NMAX * D];
__device__ __nv_bfloat16 g_Vh[NMAX * D];
__device__ float g_h[NMAX * D];               // h = x + attn residual (fp32)
__device__ __nv_bfloat16 g_hnh[NMAX * D];     // LayerNorm(h) bf16
__device__ __nv_bfloat16 g_acth[NMAX * 2 * D];// gelu bf16
__device__ __nv_bfloat16 g_Wqt[D * D];        // Wq^T bf16 [128][128]
__device__ __nv_bfloat16 g_Wkt[D * D];
__device__ __nv_bfloat16 g_Wvt[D * D];
__device__ __nv_bfloat16 g_W1t[2 * D * D];    // W1^T bf16 [256][128]
__device__ __nv_bfloat16 g_W2t[2 * D * D];    // W2^T bf16 [128][256]
__device__ int   g_cnt[NMAX];
__device__ int   g_off[NMAX + 1];
__device__ int   g_cur[NMAX];
__device__ int   g_srt[EMAX];
__device__ int   g_bsum[128];

// ---------------- sort phase ----------------
__global__ void k_hist(const int* __restrict__ ei, int E) {
    int e = blockIdx.x * blockDim.x + threadIdx.x;
    if (e < E) atomicAdd(&g_cnt[__ldg(ei + E + e)], 1);
}

__global__ __launch_bounds__(1024)
void k_scan1(int n) {
    __shared__ int ws[32];
    const int tid = threadIdx.x, lane = tid & 31, w = tid >> 5;
    int i = blockIdx.x * 1024 + tid;
    int v = 0;
    if (i < n) { v = g_cnt[i]; g_cnt[i] = 0; }
    int x = v;
#pragma unroll
    for (int o = 1; o < 32; o <<= 1) {
        int y = __shfl_up_sync(~0u, x, o);
        if (lane >= o) x += y;
    }
    if (lane == 31) ws[w] = x;
    __syncthreads();
    if (w == 0) {
        int s = ws[lane];
#pragma unroll
        for (int o = 1; o < 32; o <<= 1) {
            int y = __shfl_up_sync(~0u, s, o);
            if (lane >= o) s += y;
        }
        ws[lane] = s;
    }
    __syncthreads();
    int incl = x + (w > 0 ? ws[w - 1] : 0);
    if (i < n) g_off[i] = incl - v;
    if (tid == 1023) g_bsum[blockIdx.x] = incl;
}

__global__ __launch_bounds__(1024)
void k_scan3(int n, int E) {
    __shared__ int s_base;
    const int j = blockIdx.x;
    if (threadIdx.x < 32) {
        int acc = 0;
        for (int t = threadIdx.x; t < j; t += 32) acc += g_bsum[t];
#pragma unroll
        for (int o = 16; o > 0; o >>= 1) acc += __shfl_xor_sync(~0u, acc, o);
        if (threadIdx.x == 0) s_base = acc;
    }
    __syncthreads();
    int i = j * 1024 + threadIdx.x;
    if (i < n) {
        int o = g_off[i] + s_base;
        g_off[i] = o;
        g_cur[i] = o;
    }
    if (i == 0) g_off[n] = E;
}

__global__ void k_scatter(const int* __restrict__ ei, int E) {
    int e = blockIdx.x * blockDim.x + threadIdx.x;
    if (e >= E) return;
    int src = __ldg(ei + e);
    int dst = __ldg(ei + E + e);
    int pos = atomicAdd(&g_cur[dst], 1);
    g_srt[pos] = src;
}

// ---------------- conversions ----------------
// all 5 weight matrices -> bf16, transposed to n-major [n][k]
__global__ void k_convw(const float* __restrict__ Wq, const float* __restrict__ Wk,
                        const float* __restrict__ Wv, const float* __restrict__ W1,
                        const float* __restrict__ W2) {
    int i = blockIdx.x * blockDim.x + threadIdx.x;   // 0..32767
    if (i < 128 * 128) {
        int k = i >> 7, nn = i & 127;
        g_Wqt[nn * 128 + k] = __float2bfloat16(Wq[i]);
        g_Wkt[nn * 128 + k] = __float2bfloat16(Wk[i]);
        g_Wvt[nn * 128 + k] = __float2bfloat16(Wv[i]);
    }
    { int k = i >> 8, nn = i & 255; g_W1t[nn * 128 + k] = __float2bfloat16(W1[i]); }
    { int k = i >> 7, nn = i & 127; g_W2t[nn * 256 + k] = __float2bfloat16(W2[i]); }
}

// x (fp32) -> bf16, vectorized
__global__ void k_convx(const float* __restrict__ x, int total4) {
    int i = blockIdx.x * blockDim.x + threadIdx.x;
    if (i >= total4) return;
    float4 v = *(const float4*)(x + i * 4);
    __nv_bfloat162 p0 = __floats2bfloat162_rn(v.x, v.y);
    __nv_bfloat162 p1 = __floats2bfloat162_rn(v.z, v.w);
    *(__nv_bfloat162*)(g_xh + i * 4)     = p0;
    *(__nv_bfloat162*)(g_xh + i * 4 + 2) = p1;
}

// ---------------- mma / cp.async helpers ----------------
__device__ __forceinline__ void mma_bf16(float c[4],
    unsigned a0, unsigned a1, unsigned a2, unsigned a3,
    unsigned b0, unsigned b1)
{
    asm volatile(
        "mma.sync.aligned.m16n8k16.row.col.f32.bf16.bf16.f32 "
        "{%0,%1,%2,%3}, {%4,%5,%6,%7}, {%8,%9}, {%0,%1,%2,%3};"
        : "+f"(c[0]), "+f"(c[1]), "+f"(c[2]), "+f"(c[3])
        : "r"(a0), "r"(a1), "r"(a2), "r"(a3), "r"(b0), "r"(b1));
}

__device__ __forceinline__ void cpa16(void* smem_dst, const void* gsrc, int sz) {
    unsigned s = (unsigned)__cvta_generic_to_shared(smem_dst);
    asm volatile("cp.async.cg.shared.global [%0], [%1], 16, %2;"
                 :: "r"(s), "l"(gsrc), "r"(sz));
}

#define SMEM_BF16_BYTES (2 * (2 * 128 * 40) * 2)

// ---------------- bf16 double-buffered GEMM body ----------------
// A bf16 [nrows][KA] row-major; Bt bf16 [ncols][KA] n-major.
// EPI: 0 = fp32 +bias ; 1 = gelu(+bias)->bf16 ; 2 = +bias+R(fp32)->fp32 ; 3 = bf16 +bias
template <int KA, int EPI>
__device__ __forceinline__ void gemm_bf_body(
    const __nv_bfloat16* __restrict__ A, const __nv_bfloat16* __restrict__ Bt,
    const float* __restrict__ bias, const float* __restrict__ R,
    void* __restrict__ Cv, int nrows, int ncols, int n0)
{
    extern __shared__ __nv_bfloat16 smh[];
#define SA(b, r, c) smh[(b) * (128 * 40) + (r) * 40 + (c)]
#define SB(b, r, c) smh[2 * 128 * 40 + (b) * (128 * 40) + (r) * 40 + (c)]

    const int tid  = threadIdx.x;
    const int m0   = blockIdx.x * 128;
    const int w    = tid >> 5;
    const int lane = tid & 31;
    const int g    = lane >> 2;
    const int tig  = lane & 3;
    const int wm   = (w >> 2) * 64;
    const int wn   = (w & 3) * 32;

    float acc[4][4][4];
#pragma unroll
    for (int i = 0; i < 4; ++i)
#pragma unroll
        for (int j = 0; j < 4; ++j)
#pragma unroll
            for (int q = 0; q < 4; ++q) acc[i][j][q] = 0.0f;

    auto load_tiles = [&](int buf, int kc) {
#pragma unroll
        for (int p = 0; p < 2; ++p) {
            int seg = tid + p * 256;
            int r = seg >> 2, ko = (seg & 3) << 3;
            int sz = (m0 + r < nrows) ? 16 : 0;
            cpa16(&SA(buf, r, ko), A + (size_t)(m0 + r) * KA + kc + ko, sz);
        }
#pragma unroll
        for (int p = 0; p < 2; ++p) {
            int seg = tid + p * 256;
            int r = seg >> 2, ko = (seg & 3) << 3;
            cpa16(&SB(buf, r, ko), Bt + (size_t)(n0 + r) * KA + kc + ko, 16);
        }
    };

    constexpr int NCH = KA / 32;
    load_tiles(0, 0);
    asm volatile("cp.async.commit_group;");

#pragma unroll 1
    for (int c = 0; c < NCH; ++c) {
        if (c + 1 < NCH) {
            load_tiles((c + 1) & 1, (c + 1) * 32);
            asm volatile("cp.async.commit_group;");
            asm volatile("cp.async.wait_group 1;");
        } else {
            asm volatile("cp.async.wait_group 0;");
        }
        __syncthreads();

        const int buf = c & 1;
#pragma unroll
        for (int ks = 0; ks < 2; ++ks) {
            const int kb = ks * 16 + 2 * tig;
            unsigned af[4][4];
#pragma unroll
            for (int ms = 0; ms < 4; ++ms) {
                int row = wm + ms * 16 + g;
                af[ms][0] = *(const unsigned*)&SA(buf, row,     kb);
                af[ms][1] = *(const unsigned*)&SA(buf, row + 8, kb);
                af[ms][2] = *(const unsigned*)&SA(buf, row,     kb + 8);
                af[ms][3] = *(const unsigned*)&SA(buf, row + 8, kb + 8);
            }
            unsigned bf[4][2];
#pragma unroll
            for (int ns = 0; ns < 4; ++ns) {
                int col = wn + ns * 8 + g;
                bf[ns][0] = *(const unsigned*)&SB(buf, col, kb);
                bf[ns][1] = *(const unsigned*)&SB(buf, col, kb + 8);
            }
#pragma unroll
            for (int ms = 0; ms < 4; ++ms)
#pragma unroll
                for (int ns = 0; ns < 4; ++ns)
                    mma_bf16(acc[ms][ns], af[ms][0], af[ms][1], af[ms][2], af[ms][3],
                             bf[ns][0], bf[ns][1]);
        }
        __syncthreads();
    }

#pragma unroll
    for (int ms = 0; ms < 4; ++ms) {
        int row0 = m0 + wm + ms * 16 + g;
#pragma unroll
        for (int half = 0; half < 2; ++half) {
            int row = row0 + half * 8;
            if (row >= nrows) continue;
#pragma unroll
            for (int ns = 0; ns < 4; ++ns) {
                int col = n0 + wn + ns * 8 + tig * 2;
                float v0 = acc[ms][ns][half * 2 + 0] + __ldg(bias + col);
                float v1 = acc[ms][ns][half * 2 + 1] + __ldg(bias + col + 1);
                if (EPI == 1) {
                    v0 = 0.5f * v0 * (1.0f + erff(v0 * 0.70710678118654752f));
                    v1 = 0.5f * v1 * (1.0f + erff(v1 * 0.70710678118654752f));
                    __nv_bfloat162 p = __floats2bfloat162_rn(v0, v1);
                    *(__nv_bfloat162*)((__nv_bfloat16*)Cv + (size_t)row * ncols + col) = p;
                } else if (EPI == 3) {
                    __nv_bfloat162 p = __floats2bfloat162_rn(v0, v1);
                    *(__nv_bfloat162*)((__nv_bfloat16*)Cv + (size_t)row * ncols + col) = p;
                } else if (EPI == 2) {
                    const float2 r2 = *(const float2*)(R + (size_t)row * ncols + col);
                    *(float2*)((float*)Cv + (size_t)row * ncols + col) =
                        make_float2(v0 + r2.x, v1 + r2.y);
                } else {
                    *(float2*)((float*)Cv + (size_t)row * ncols + col) = make_float2(v0, v1);
                }
            }
        }
    }
#undef SA
#undef SB
}

template <int KA, int EPI>
__global__ __launch_bounds__(256)
void k_gemm_bf(const __nv_bfloat16* __restrict__ A, const __nv_bfloat16* __restrict__ Bt,
               const float* __restrict__ bias, const float* __restrict__ R,
               void* __restrict__ Cv, int nrows, int ncols)
{
    gemm_bf_body<KA, EPI>(A, Bt, bias, R, Cv, nrows, ncols, blockIdx.y * 128);
}

__global__ __launch_bounds__(256)
void k_gemm_qkv_bf(const float* __restrict__ bq, const float* __restrict__ bk,
                   const float* __restrict__ bv, int nrows)
{
    if (blockIdx.z == 0)
        gemm_bf_body<128, 0>(g_xh, g_Wqt, bq, nullptr, g_Q, nrows, 128, 0);
    else if (blockIdx.z == 1)
        gemm_bf_body<128, 3>(g_xh, g_Wkt, bk, nullptr, g_Kh, nrows, 128, 0);
    else
        gemm_bf_body<128, 3>(g_xh, g_Wvt, bv, nullptr, g_Vh, nrows, 128, 0);
}

// ---------------- fused attention + residual + LayerNorm, warp per dst ----------------
__device__ __forceinline__ float2 bf2f(unsigned u) {
    __nv_bfloat162 h = *reinterpret_cast<__nv_bfloat162*>(&u);
    return __bfloat1622float2(h);
}

__global__ __launch_bounds__(256)
void k_attn(const float* __restrict__ x,
            const float* __restrict__ lng, const float* __restrict__ lnb, int n)
{
    int row = (blockIdx.x * blockDim.x + threadIdx.x) >> 5;
    if (row >= n) return;
    const int lane = threadIdx.x & 31;
    const size_t lo = (size_t)lane * 4;

    float4 q = *(const float4*)(g_Q + (size_t)row * D + lo);
    float ax = 0.f, ay = 0.f, az = 0.f, aw = 0.f, den = 0.f;

    int beg = g_off[row], end = g_off[row + 1];
    int j = beg;

    // 4-edge software pipeline: batch indices, then batch all 8 K/V loads
    for (; j + 3 < end; j += 4) {
        int s0 = __ldg(g_srt + j);
        int s1 = __ldg(g_srt + j + 1);
        int s2 = __ldg(g_srt + j + 2);
        int s3 = __ldg(g_srt + j + 3);
        uint2 kr0 = *(const uint2*)(g_Kh + (size_t)s0 * D + lo);
        uint2 kr1 = *(const uint2*)(g_Kh + (size_t)s1 * D + lo);
        uint2 kr2 = *(const uint2*)(g_Kh + (size_t)s2 * D + lo);
        uint2 kr3 = *(const uint2*)(g_Kh + (size_t)s3 * D + lo);
        uint2 vr0 = *(const uint2*)(g_Vh + (size_t)s0 * D + lo);
        uint2 vr1 = *(const uint2*)(g_Vh + (size_t)s1 * D + lo);
        uint2 vr2 = *(const uint2*)(g_Vh + (size_t)s2 * D + lo);
        uint2 vr3 = *(const uint2*)(g_Vh + (size_t)s3 * D + lo);

        float2 k0a = bf2f(kr0.x), k0b = bf2f(kr0.y);
        float2 k1a = bf2f(kr1.x), k1b = bf2f(kr1.y);
        float2 k2a = bf2f(kr2.x), k2b = bf2f(kr2.y);
        float2 k3a = bf2f(kr3.x), k3b = bf2f(kr3.y);
        float d0 = q.x * k0a.x + q.y * k0a.y + q.z * k0b.x + q.w * k0b.y;
        float d1 = q.x * k1a.x + q.y * k1a.y + q.z * k1b.x + q.w * k1b.y;
        float d2 = q.x * k2a.x + q.y * k2a.y + q.z * k2b.x + q.w * k2b.y;
        float d3 = q.x * k3a.x + q.y * k3a.y + q.z * k3b.x + q.w * k3b.y;
        d0 += __shfl_xor_sync(~0u, d0, 1);
        d1 += __shfl_xor_sync(~0u, d1, 1);
        d2 += __shfl_xor_sync(~0u, d2, 1);
        d3 += __shfl_xor_sync(~0u, d3, 1);
        d0 += __shfl_xor_sync(~0u, d0, 2);
        d1 += __shfl_xor_sync(~0u, d1, 2);
        d2 += __shfl_xor_sync(~0u, d2, 2);
        d3 += __shfl_xor_sync(~0u, d3, 2);
        float e0 = __expf(d0 * 0.25f);
        float e1 = __expf(d1 * 0.25f);
        float e2 = __expf(d2 * 0.25f);
        float e3 = __expf(d3 * 0.25f);
        den += (e0 + e1) + (e2 + e3);
        float2 v0a = bf2f(vr0.x), v0b = bf2f(vr0.y);
        float2 v1a = bf2f(vr1.x), v1b = bf2f(vr1.y);
        float2 v2a = bf2f(vr2.x), v2b = bf2f(vr2.y);
        float2 v3a = bf2f(vr3.x), v3b = bf2f(vr3.y);
        ax += e0 * v0a.x + e1 * v1a.x + e2 * v2a.x + e3 * v3a.x;
        ay += e0 * v0a.y + e1 * v1a.y + e2 * v2a.y + e3 * v3a.y;
        az += e0 * v0b.x + e1 * v1b.x + e2 * v2b.x + e3 * v3b.x;
        aw += e0 * v0b.y + e1 * v1b.y + e2 * v2b.y + e3 * v3b.y;
    }
    for (; j < end; ++j) {
        int s0 = __ldg(g_srt + j);
        uint2 kr0 = *(const uint2*)(g_Kh + (size_t)s0 * D + lo);
        uint2 vr0 = *(const uint2*)(g_Vh + (size_t)s0 * D + lo);
        float2 ka = bf2f(kr0.x), kb = bf2f(kr0.y);
        float d0 = q.x * ka.x + q.y * ka.y + q.z * kb.x + q.w * kb.y;
        d0 += __shfl_xor_sync(~0u, d0, 1);
        d0 += __shfl_xor_sync(~0u, d0, 2);
        float e0 = __expf(d0 * 0.25f);
        den += e0;
        float2 va = bf2f(vr0.x), vb = bf2f(vr0.y);
        ax += e0 * va.x; ay += e0 * va.y;
        az += e0 * vb.x; aw += e0 * vb.y;
    }

    float inv = 1.0f / (den + 1e-16f);
    float4 xr = *(const float4*)(x + (size_t)row * D + lo);
    float4 hv = make_float4(xr.x + ax * inv, xr.y + ay * inv,
                            xr.z + az * inv, xr.w + aw * inv);
    *(float4*)(g_h + (size_t)row * D + lo) = hv;

    // fused LayerNorm -> bf16
    float s = hv.x + hv.y + hv.z + hv.w;
#pragma unroll
    for (int o = 16; o > 0; o >>= 1) s += __shfl_xor_sync(~0u, s, o);
    float mu = s * (1.0f / 128.0f);
    float dx = hv.x - mu, dy = hv.y - mu, dz = hv.z - mu, dw = hv.w - mu;
    float vs = dx * dx + dy * dy + dz * dz + dw * dw;
#pragma unroll
    for (int o = 16; o > 0; o >>= 1) vs += __shfl_xor_sync(~0u, vs, o);
    float r = rsqrtf(vs * (1.0f / 128.0f) + 1e-5f);
    float4 gg = *(const float4*)(lng + lo);
    float4 bb = *(const float4*)(lnb + lo);
    __nv_bfloat162 o0 = __floats2bfloat162_rn(dx * r * gg.x + bb.x, dy * r * gg.y + bb.y);
    __nv_bfloat162 o1 = __floats2bfloat162_rn(dz * r * gg.z + bb.z, dw * r * gg.w + bb.w);
    *(__nv_bfloat162*)(g_hnh + (size_t)row * D + lo)     = o0;
    *(__nv_bfloat162*)(g_hnh + (size_t)row * D + lo + 2) = o1;
}

// ---------------- launch ----------------
extern "C" void kernel_launch(void* const* d_in, const int* in_sizes, int n_in,
                              void* d_out, int out_size) {
    const float* x    = (const float*)d_in[0];
    const int*   ei   = (const int*)  d_in[1];
    const float* Wq   = (const float*)d_in[2];
    const float* bq   = (const float*)d_in[3];
    const float* Wk   = (const float*)d_in[4];
    const float* bk   = (const float*)d_in[5];
    const float* Wv   = (const float*)d_in[6];
    const float* bv   = (const float*)d_in[7];
    const float* ln_g = (const float*)d_in[8];
    const float* ln_b = (const float*)d_in[9];
    const float* W1   = (const float*)d_in[10];
    const float* b1   = (const float*)d_in[11];
    const float* W2   = (const float*)d_in[12];
    const float* b2   = (const float*)d_in[13];
    float* out = (float*)d_out;

    const int n = in_sizes[0] / D;
    const int E = in_sizes[1] / 2;

    static bool inited = false;
    static __nv_bfloat16 *phn, *pact, *pW1t, *pW2t;
    static float *ph;
    static cudaStream_t s1, s2;
    static cudaEvent_t evFork, evSort, evW;
    if (!inited) {
        cudaGetSymbolAddress((void**)&phn,  g_hnh);
        cudaGetSymbolAddress((void**)&pact, g_acth);
        cudaGetSymbolAddress((void**)&pW1t, g_W1t);
        cudaGetSymbolAddress((void**)&pW2t, g_W2t);
        cudaGetSymbolAddress((void**)&ph,   g_h);
        cudaStreamCreateWithFlags(&s1, cudaStreamNonBlocking);
        cudaStreamCreateWithFlags(&s2, cudaStreamNonBlocking);
        cudaEventCreateWithFlags(&evFork, cudaEventDisableTiming);
        cudaEventCreateWithFlags(&evSort, cudaEventDisableTiming);
        cudaEventCreateWithFlags(&evW,    cudaEventDisableTiming);
        inited = true;
    }

    // fork side streams off the main (captured) stream
    cudaEventRecord(evFork, 0);
    cudaStreamWaitEvent(s1, evFork, 0);
    cudaStreamWaitEvent(s2, evFork, 0);

    // --- side stream 1: counting sort of edges by dst ---
    const int nb = (n + 1023) / 1024;
    k_hist<<<(E + 255) / 256, 256, 0, s1>>>(ei, E);
    k_scan1<<<nb, 1024, 0, s1>>>(n);
    k_scan3<<<nb, 1024, 0, s1>>>(n, E);
    k_scatter<<<(E + 255) / 256, 256, 0, s1>>>(ei, E);
    cudaEventRecord(evSort, s1);

    // --- side stream 2: weight conversion (all 5 matrices -> bf16 n-major) ---
    k_convw<<<128, 256, 0, s2>>>(Wq, Wk, Wv, W1, W2);
    cudaEventRecord(evW, s2);

    // --- main: x -> bf16, then fused QKV (bf16 mma) ---
    k_convx<<<(n * D / 4 + 255) / 256, 256>>>(x, n * D / 4);
    cudaStreamWaitEvent(0, evW, 0);
    dim3 gq((n + 127) / 128, 1, 3);
    k_gemm_qkv_bf<<<gq, 256, SMEM_BF16_BYTES>>>(bq, bk, bv, n);

    // join sort, fused attention + residual + LayerNorm
    cudaStreamWaitEvent(0, evSort, 0);
    k_attn<<<(n * 32 + 255) / 256, 256>>>(x, ln_g, ln_b, n);

    // FFN (bf16 mma)
    dim3 gf1((n + 127) / 128, 2);
    k_gemm_bf<128, 1><<<gf1, 256, SMEM_BF16_BYTES>>>(phn, pW1t, b1, nullptr, pact, n, 2 * D);

    dim3 gf2((n + 127) / 128, 1);
    k_gemm_bf<256, 2><<<gf2, 256, SMEM_BF16_BYTES>>>(pact, pW2t, b2, ph, out, n, D);
}